// round 6
// baseline (speedup 1.0000x reference)
#include <cuda_runtime.h>
#include <math.h>

typedef unsigned long long ull;

// Problem constants
#define B   2
#define L   768
#define H   12
#define DH  64
#define D   8
#define DS  8
#define E   768
#define BH  (B*H)

#define SQT 24            // stats q-tiles: 32 rows per block
#define CQT 96            // combine q-tiles: 8 rows per block
#define NPART (BH*D*SQT)

#define RSQRT_DS 0.35355339059327373f   // 1/sqrt(8)

// Scratch (static device arrays; no runtime allocation)
__device__ float g_Q[BH*D*L*DS];     // [b,h,d,l,s]
__device__ float g_K[BH*D*L*DS];     // [b,h,d,l,s]
__device__ float g_V[BH*L*DH];       // [b,h,l,dh]
__device__ float g_invZ[BH*D*L];     // per-row 1/Z
__device__ float g_part[NPART*3];    // per-block partial sums (hhi, max, ent)
__device__ float g_stats[B*D*4];     // var, max, ent, hhi
__device__ float g_w[B*D];           // depth weights

// ---------------------------------------------------------------------------
// f32x2 packed helpers
// ---------------------------------------------------------------------------
__device__ __forceinline__ ull ffma2(ull a, ull b, ull c) {
    ull d_; asm("fma.rn.f32x2 %0, %1, %2, %3;" : "=l"(d_) : "l"(a), "l"(b), "l"(c));
    return d_;
}
__device__ __forceinline__ ull fmul2(ull a, ull b) {
    ull d_; asm("mul.rn.f32x2 %0, %1, %2;" : "=l"(d_) : "l"(a), "l"(b));
    return d_;
}
__device__ __forceinline__ float2 unpk(ull v) {
    float2 f; asm("mov.b64 {%0, %1}, %2;" : "=f"(f.x), "=f"(f.y) : "l"(v));
    return f;
}

// ---------------------------------------------------------------------------
// Kernel 1: QKV projections with f32x2.  Tile 128(M) x 64(N), K-step 16.
// 256 threads (16x16), micro-tile 8 rows (4 row-pairs) x 4 cols per thread.
// grid: (E/64, (B*L)/128, 3)
// ---------------------------------------------------------------------------
__global__ __launch_bounds__(256)
void qkv_gemm(const float* __restrict__ X,
              const float* __restrict__ Wq, const float* __restrict__ bq,
              const float* __restrict__ Wk, const float* __restrict__ bk,
              const float* __restrict__ Wv, const float* __restrict__ bv)
{
    int z = blockIdx.z;
    const float* Wm = (z == 0) ? Wq : (z == 1) ? Wk : Wv;
    const float* bm = (z == 0) ? bq : (z == 1) ? bk : bv;

    __shared__ float  As[16][132];     // k-major, m contiguous
    __shared__ float2 Ws2[16][66];     // duplicated B operand

    int tx = threadIdx.x & 15;
    int ty = threadIdx.x >> 4;
    int tid = threadIdx.x;
    int rowBase = blockIdx.y * 128;
    int colBase = blockIdx.x * 64;

    ull acc[4][4];
    #pragma unroll
    for (int i = 0; i < 4; i++)
        #pragma unroll
        for (int j = 0; j < 4; j++) acc[i][j] = 0ull;

    for (int kk = 0; kk < E; kk += 16) {
        __syncthreads();
        {
            int r = tid >> 1, kc = (tid & 1) * 8;
            const float* xp = X + (size_t)(rowBase + r) * E + kk + kc;
            float4 x0 = *(const float4*)xp;
            float4 x1 = *(const float4*)(xp + 4);
            As[kc + 0][r] = x0.x; As[kc + 1][r] = x0.y;
            As[kc + 2][r] = x0.z; As[kc + 3][r] = x0.w;
            As[kc + 4][r] = x1.x; As[kc + 5][r] = x1.y;
            As[kc + 6][r] = x1.z; As[kc + 7][r] = x1.w;

            int t = tid >> 4, n = (tid & 15) * 4;
            const float* wp = Wm + (size_t)(kk + t) * E + colBase + n;
            float4 wv = *(const float4*)wp;
            Ws2[t][n + 0] = make_float2(wv.x, wv.x);
            Ws2[t][n + 1] = make_float2(wv.y, wv.y);
            Ws2[t][n + 2] = make_float2(wv.z, wv.z);
            Ws2[t][n + 3] = make_float2(wv.w, wv.w);
        }
        __syncthreads();
        #pragma unroll
        for (int t = 0; t < 16; t++) {
            ulonglong2 a0 = *(const ulonglong2*)&As[t][ty * 8];
            ulonglong2 a1 = *(const ulonglong2*)&As[t][ty * 8 + 4];
            ulonglong2 b0 = *(const ulonglong2*)&Ws2[t][tx * 4];
            ulonglong2 b1 = *(const ulonglong2*)&Ws2[t][tx * 4 + 2];
            ull ap[4] = {a0.x, a0.y, a1.x, a1.y};
            ull bd[4] = {b0.x, b0.y, b1.x, b1.y};
            #pragma unroll
            for (int ip = 0; ip < 4; ip++)
                #pragma unroll
                for (int j = 0; j < 4; j++)
                    acc[ip][j] = ffma2(ap[ip], bd[j], acc[ip][j]);
        }
    }

    float bias[4];
    #pragma unroll
    for (int j = 0; j < 4; j++) bias[j] = bm[colBase + tx * 4 + j];

    int c0 = colBase + tx * 4;
    int h = c0 >> 6;
    int dd = (c0 >> 3) & 7;
    int s0 = c0 & 7;

    #pragma unroll
    for (int ip = 0; ip < 4; ip++) {
        int l0g = rowBase + ty * 8 + ip * 2;
        float2 p0 = unpk(acc[ip][0]), p1 = unpk(acc[ip][1]);
        float2 p2 = unpk(acc[ip][2]), p3 = unpk(acc[ip][3]);
        float4 r0 = make_float4(p0.x + bias[0], p1.x + bias[1], p2.x + bias[2], p3.x + bias[3]);
        float4 r1 = make_float4(p0.y + bias[0], p1.y + bias[1], p2.y + bias[2], p3.y + bias[3]);
        #pragma unroll
        for (int rr = 0; rr < 2; rr++) {
            int lg = l0g + rr;
            int bb = lg / L, l = lg - bb * L;
            float4 v = rr ? r1 : r0;
            if (z < 2) {
                float* dst = (z == 0 ? g_Q : g_K)
                    + (((size_t)(bb * H + h) * D + dd) * L + l) * 8 + s0;
                *(float4*)dst = v;
            } else {
                float* dst = g_V + ((size_t)(bb * H + h) * L + l) * 64 + (tx * 4);
                *(float4*)dst = v;
            }
        }
    }
}

// ---------------------------------------------------------------------------
// Kernel 2: statistics pass (single loop, no-rescale softmax, one exp).
// Each warp: 4 q rows x full K, lane strided over k.  Block = 32 rows.
// grid: (SQT, D, BH), 256 threads.
// ---------------------------------------------------------------------------
__global__ __launch_bounds__(256)
void attn_stats(const float* __restrict__ mask)
{
    int bh = blockIdx.z, d = blockIdx.y, qt = blockIdx.x;
    int w = threadIdx.x >> 5, lane = threadIdx.x & 31;
    int b = bh / H;
    int q0 = qt * 32 + w * 4;

    const float* Kd = g_K + ((size_t)(bh * D + d) * L) * DS;
    const float* Qd = g_Q + ((size_t)(bh * D + d) * L) * DS;
    const float* mrow = mask + b * L;

    ull qp[4][4];
    #pragma unroll
    for (int r = 0; r < 4; r++) {
        const ulonglong2* qq = (const ulonglong2*)(Qd + (size_t)(q0 + r) * 8);
        ulonglong2 a = qq[0], bb2 = qq[1];
        qp[r][0] = a.x; qp[r][1] = a.y; qp[r][2] = bb2.x; qp[r][3] = bb2.y;
    }

    float Z[4] = {0, 0, 0, 0}, S2[4] = {0, 0, 0, 0};
    float ES[4] = {0, 0, 0, 0}, EM[4] = {0, 0, 0, 0};

    #pragma unroll 6
    for (int j = 0; j < 24; j++) {
        int k = j * 32 + lane;
        const ulonglong2* kp = (const ulonglong2*)(Kd + (size_t)k * 8);
        ulonglong2 kv0 = kp[0], kv1 = kp[1];
        float mk = __ldg(mrow + k);
        #pragma unroll
        for (int r = 0; r < 4; r++) {
            ull t = ffma2(qp[r][0], kv0.x,
                    ffma2(qp[r][1], kv0.y,
                    ffma2(qp[r][2], kv1.x,
                    fmul2(qp[r][3], kv1.y))));
            float2 u = unpk(t);
            float s = fmaf(u.x + u.y, RSQRT_DS, mk);
            float e = __expf(s);
            Z[r] += e;
            S2[r] = fmaf(e, e, S2[r]);
            ES[r] = fmaf(e, s, ES[r]);
            EM[r] = fmaxf(EM[r], e);
        }
    }

    #pragma unroll
    for (int r = 0; r < 4; r++) {
        #pragma unroll
        for (int o = 16; o; o >>= 1) {
            Z[r]  += __shfl_xor_sync(0xffffffffu, Z[r],  o);
            S2[r] += __shfl_xor_sync(0xffffffffu, S2[r], o);
            ES[r] += __shfl_xor_sync(0xffffffffu, ES[r], o);
            EM[r]  = fmaxf(EM[r], __shfl_xor_sync(0xffffffffu, EM[r], o));
        }
    }

    __shared__ float sH[8], sM[8], sE[8];
    if (lane == 0) {
        float hh = 0, mm = 0, ee = 0;
        #pragma unroll
        for (int r = 0; r < 4; r++) {
            float invZ = 1.f / Z[r];
            g_invZ[((size_t)(bh * D + d)) * L + q0 + r] = invZ;
            hh += S2[r] * invZ * invZ;
            mm += EM[r] * invZ;
            ee += __logf(Z[r]) - ES[r] * invZ;
        }
        sH[w] = hh; sM[w] = mm; sE[w] = ee;
    }
    __syncthreads();
    if (threadIdx.x == 0) {
        float hh = 0, mm = 0, ee = 0;
        #pragma unroll
        for (int ww = 0; ww < 8; ww++) { hh += sH[ww]; mm += sM[ww]; ee += sE[ww]; }
        size_t idx = ((size_t)(bh * D + d) * SQT + qt) * 3;
        g_part[idx + 0] = hh;  // sum of row hhi (= sum p^2)
        g_part[idx + 1] = mm;  // sum of row max
        g_part[idx + 2] = ee;  // sum of row entropy
    }
}

// ---------------------------------------------------------------------------
// Kernel 3: reduce partials over (h, qtile) per (b,d). Double precision.
// grid: B*D blocks, 256 threads.
// ---------------------------------------------------------------------------
__global__ __launch_bounds__(256)
void reduce_stats()
{
    int bd = blockIdx.x;
    int b = bd / D, d = bd % D;
    int t = threadIdx.x;

    double s2 = 0, mx = 0, en = 0;
    for (int i = t; i < H * SQT; i += 256) {
        int h = i / SQT, qt = i % SQT;
        size_t idx = ((size_t)((b * H + h) * D + d) * SQT + qt) * 3;
        s2 += (double)g_part[idx + 0];
        mx += (double)g_part[idx + 1];
        en += (double)g_part[idx + 2];
    }
    __shared__ double sh0[256], sh1[256], sh2[256];
    sh0[t] = s2; sh1[t] = mx; sh2[t] = en;
    __syncthreads();
    for (int o = 128; o; o >>= 1) {
        if (t < o) { sh0[t] += sh0[t+o]; sh1[t] += sh1[t+o]; sh2[t] += sh2[t+o]; }
        __syncthreads();
    }
    if (t == 0) {
        double n = (double)H * (double)L;
        double S2m = sh0[0] / n;
        g_stats[(b * D + d) * 4 + 0] = (float)((S2m - 1.0 / (double)L) / (double)(L - 1));
        g_stats[(b * D + d) * 4 + 1] = (float)(sh1[0] / n);
        g_stats[(b * D + d) * 4 + 2] = (float)(sh2[0] / n);
        g_stats[(b * D + d) * 4 + 3] = (float)S2m;
    }
}

// ---------------------------------------------------------------------------
// Kernel 4: min-max norm over D, score, softmax -> weights. Tiny.
// ---------------------------------------------------------------------------
__global__ void compute_weights()
{
    int b = blockIdx.x;
    if (threadIdx.x != 0) return;

    float st[4][D], nrm[4][D];
    for (int d = 0; d < D; d++)
        for (int j = 0; j < 4; j++) st[j][d] = g_stats[(b * D + d) * 4 + j];

    for (int j = 0; j < 4; j++) {
        float mn = st[j][0], mx = st[j][0];
        for (int d = 1; d < D; d++) { mn = fminf(mn, st[j][d]); mx = fmaxf(mx, st[j][d]); }
        float den = fmaxf(mx - mn, 1e-12f);
        for (int d = 0; d < D; d++) nrm[j][d] = (st[j][d] - mn) / den;
    }
    float sc[D], mxs = -1e30f;
    for (int d = 0; d < D; d++) {
        sc[d] = 2.5f * (0.5f * nrm[0][d] + 0.3f * nrm[1][d]
                        + 0.2f * nrm[3][d] - 0.4f * nrm[2][d]);
        mxs = fmaxf(mxs, sc[d]);
    }
    float Z = 0.f, e[D];
    for (int d = 0; d < D; d++) { e[d] = expf(sc[d] - mxs); Z += e[d]; }
    for (int d = 0; d < D; d++) g_w[b * D + d] = e[d] / Z;
}

// ---------------------------------------------------------------------------
// Kernel 5: combine pass -> attn4.  No reductions: uses stored invZ.
// Block = 8 q rows of one bh; warp w owns k in [w*96, w*96+96).
// Per element: dot -> exp -> fma.  grid: (CQT, BH), 256 threads.
// ---------------------------------------------------------------------------
__global__ __launch_bounds__(256)
void attn_combine(const float* __restrict__ mask, float* __restrict__ out_attn)
{
    int bh = blockIdx.y;
    int w = threadIdx.x >> 5, lane = threadIdx.x & 31;
    int b = bh / H;
    int q0 = blockIdx.x * 8;
    int kb = w * 96;
    const float* mrow = mask + b * L;

    __shared__ float sf[8][8];   // [r][d] = w_d * invZ(row r, depth d)
    if (threadIdx.x < 64) {
        int r = threadIdx.x >> 3, d = threadIdx.x & 7;
        sf[r][d] = g_w[b * D + d] *
                   g_invZ[((size_t)(bh * D + d)) * L + q0 + r];
    }
    __syncthreads();

    float mk[3];
    #pragma unroll
    for (int j = 0; j < 3; j++) mk[j] = __ldg(mrow + kb + j * 32 + lane);

    float acc[8][3];
    #pragma unroll
    for (int r = 0; r < 8; r++)
        #pragma unroll
        for (int j = 0; j < 3; j++) acc[r][j] = 0.f;

    for (int d = 0; d < D; d++) {
        const float* Kd = g_K + ((size_t)(bh * D + d) * L) * DS;
        const float* Qd = g_Q + ((size_t)(bh * D + d) * L) * DS;
        ull qp[8][4];
        #pragma unroll
        for (int r = 0; r < 8; r++) {
            const ulonglong2* qq = (const ulonglong2*)(Qd + (size_t)(q0 + r) * 8);
            ulonglong2 a = qq[0], bb2 = qq[1];
            qp[r][0] = a.x; qp[r][1] = a.y; qp[r][2] = bb2.x; qp[r][3] = bb2.y;
        }
        float fr[8];
        #pragma unroll
        for (int r = 0; r < 8; r++) fr[r] = sf[r][d];

        #pragma unroll
        for (int j = 0; j < 3; j++) {
            int k = kb + j * 32 + lane;
            const ulonglong2* kp = (const ulonglong2*)(Kd + (size_t)k * 8);
            ulonglong2 kv0 = kp[0], kv1 = kp[1];
            #pragma unroll
            for (int r = 0; r < 8; r++) {
                ull t = ffma2(qp[r][0], kv0.x,
                        ffma2(qp[r][1], kv0.y,
                        ffma2(qp[r][2], kv1.x,
                        fmul2(qp[r][3], kv1.y))));
                float2 u = unpk(t);
                float s = fmaf(u.x + u.y, RSQRT_DS, mk[j]);
                float e = __expf(s);
                acc[r][j] = fmaf(e, fr[r], acc[r][j]);
            }
        }
    }

    #pragma unroll
    for (int r = 0; r < 8; r++) {
        float* row = out_attn + ((size_t)bh * L + q0 + r) * L;
        #pragma unroll
        for (int j = 0; j < 3; j++) row[kb + j * 32 + lane] = acc[r][j];
    }
}

// ---------------------------------------------------------------------------
// Kernel 6: ctx = attn4 @ V per (b,h), f32x2.  Tile 128(M) x 64(N=DH).
// grid: (L/128, BH), 256 threads, micro 8x4.
// ---------------------------------------------------------------------------
__global__ __launch_bounds__(256)
void ctx_gemm(const float* __restrict__ attn4, float* __restrict__ out)
{
    int bh = blockIdx.y;
    int b = bh / H, h = bh % H;
    int rowBase = blockIdx.x * 128;

    __shared__ float  As[16][132];
    __shared__ float2 Vs2[16][66];

    int tx = threadIdx.x & 15;
    int ty = threadIdx.x >> 4;
    int tid = threadIdx.x;

    const float* A  = attn4 + (size_t)bh * L * L;
    const float* Vp = g_V + (size_t)bh * L * DH;

    ull acc[4][4];
    #pragma unroll
    for (int i = 0; i < 4; i++)
        #pragma unroll
        for (int j = 0; j < 4; j++) acc[i][j] = 0ull;

    for (int kk = 0; kk < L; kk += 16) {
        __syncthreads();
        {
            int r = tid >> 1, kc = (tid & 1) * 8;
            const float* ap = A + (size_t)(rowBase + r) * L + kk + kc;
            float4 a0 = *(const float4*)ap;
            float4 a1 = *(const float4*)(ap + 4);
            As[kc + 0][r] = a0.x; As[kc + 1][r] = a0.y;
            As[kc + 2][r] = a0.z; As[kc + 3][r] = a0.w;
            As[kc + 4][r] = a1.x; As[kc + 5][r] = a1.y;
            As[kc + 6][r] = a1.z; As[kc + 7][r] = a1.w;

            int t = tid >> 4, n = (tid & 15) * 4;
            const float* vp = Vp + (size_t)(kk + t) * DH + n;
            float4 vv = *(const float4*)vp;
            Vs2[t][n + 0] = make_float2(vv.x, vv.x);
            Vs2[t][n + 1] = make_float2(vv.y, vv.y);
            Vs2[t][n + 2] = make_float2(vv.z, vv.z);
            Vs2[t][n + 3] = make_float2(vv.w, vv.w);
        }
        __syncthreads();
        #pragma unroll
        for (int t = 0; t < 16; t++) {
            ulonglong2 a0 = *(const ulonglong2*)&As[t][ty * 8];
            ulonglong2 a1 = *(const ulonglong2*)&As[t][ty * 8 + 4];
            ulonglong2 b0 = *(const ulonglong2*)&Vs2[t][tx * 4];
            ulonglong2 b1 = *(const ulonglong2*)&Vs2[t][tx * 4 + 2];
            ull ap2[4] = {a0.x, a0.y, a1.x, a1.y};
            ull bd[4]  = {b0.x, b0.y, b1.x, b1.y};
            #pragma unroll
            for (int ip = 0; ip < 4; ip++)
                #pragma unroll
                for (int j = 0; j < 4; j++)
                    acc[ip][j] = ffma2(ap2[ip], bd[j], acc[ip][j]);
        }
    }

    #pragma unroll
    for (int ip = 0; ip < 4; ip++) {
        int l0 = rowBase + ty * 8 + ip * 2;
        float2 p0 = unpk(acc[ip][0]), p1 = unpk(acc[ip][1]);
        float2 p2 = unpk(acc[ip][2]), p3 = unpk(acc[ip][3]);
        float4 r0 = make_float4(p0.x, p1.x, p2.x, p3.x);
        float4 r1 = make_float4(p0.y, p1.y, p2.y, p3.y);
        float* d0 = out + ((size_t)(b * L + l0)) * E + h * DH + tx * 4;
        float* d1 = out + ((size_t)(b * L + l0 + 1)) * E + h * DH + tx * 4;
        *(float4*)d0 = r0;
        *(float4*)d1 = r1;
    }
}

// ---------------------------------------------------------------------------
extern "C" void kernel_launch(void* const* d_in, const int* in_sizes, int n_in,
                              void* d_out, int out_size)
{
    const float* X    = (const float*)d_in[0];
    const float* mask = (const float*)d_in[1];
    const float* Wq   = (const float*)d_in[2];
    const float* bq   = (const float*)d_in[3];
    const float* Wk   = (const float*)d_in[4];
    const float* bk   = (const float*)d_in[5];
    const float* Wv   = (const float*)d_in[6];
    const float* bv   = (const float*)d_in[7];

    float* out   = (float*)d_out;
    float* ctx   = out;                          // [B, L, E]
    float* attn4 = out + (size_t)B * L * E;      // [B, H, L, L]

    qkv_gemm<<<dim3(E / 64, (B * L) / 128, 3), 256>>>(X, Wq, bq, Wk, bk, Wv, bv);
    attn_stats<<<dim3(SQT, D, BH), 256>>>(mask);
    reduce_stats<<<B * D, 256>>>();
    compute_weights<<<B, 32>>>();
    attn_combine<<<dim3(CQT, BH), 256>>>(mask, attn4);
    ctx_gemm<<<dim3(L / 128, BH), 256>>>(attn4, ctx);
}

// round 10
// speedup vs baseline: 2.1710x; 2.1710x over previous
#include <cuda_runtime.h>
#include <cuda_bf16.h>
#include <math.h>

typedef unsigned long long ull;

#define B   2
#define L   768
#define H   12
#define DH  64
#define D   8
#define DS  8
#define E   768
#define BH  (B*H)

#define SQT 24
#define CQT 96
#define NPART (BH*D*SQT)

#define SCALE2 0.51006972f     // (1/sqrt(8)) * log2(e)
#define LOG2E  1.4426950408889634f
#define LN2    0.6931471805599453f

__device__ float g_Q[BH*D*L*DS];
__device__ float g_K[BH*D*L*DS];
__device__ float g_V[BH*L*DH];
__device__ float g_invZ[BH*D*L];
__device__ float g_part[NPART*3];
__device__ float g_w[B*D];

// ---------------- f32x2 + math helpers ----------------
__device__ __forceinline__ ull ffma2(ull a, ull b, ull c) {
    ull d_; asm("fma.rn.f32x2 %0, %1, %2, %3;" : "=l"(d_) : "l"(a), "l"(b), "l"(c));
    return d_;
}
__device__ __forceinline__ ull fmul2(ull a, ull b) {
    ull d_; asm("mul.rn.f32x2 %0, %1, %2;" : "=l"(d_) : "l"(a), "l"(b));
    return d_;
}
__device__ __forceinline__ float2 unpk(ull v) {
    float2 f; asm("mov.b64 {%0, %1}, %2;" : "=f"(f.x), "=f"(f.y) : "l"(v));
    return f;
}
__device__ __forceinline__ float ex2f(float x) {
    float r; asm("ex2.approx.ftz.f32 %0, %1;" : "=f"(r) : "f"(x));
    return r;
}

// ---------------- bf16 split/pack + mma.sync ----------------
__device__ __forceinline__ void split_bf(float x, unsigned short& hi, unsigned short& lo) {
    __nv_bfloat16 h = __float2bfloat16_rn(x);
    hi = __bfloat16_as_ushort(h);
    lo = __bfloat16_as_ushort(__float2bfloat16_rn(x - __bfloat162float(h)));
}
__device__ __forceinline__ unsigned pk(unsigned short a, unsigned short b) {
    return (unsigned)a | ((unsigned)b << 16);
}
// D += A(bf16 m16k16 row) * B(bf16 k16n8 col)
__device__ __forceinline__ void mma_bf16(float* c, const unsigned* a, const unsigned* b) {
    asm volatile(
        "mma.sync.aligned.m16n8k16.row.col.f32.bf16.bf16.f32 "
        "{%0,%1,%2,%3}, {%4,%5,%6,%7}, {%8,%9}, {%0,%1,%2,%3};"
        : "+f"(c[0]), "+f"(c[1]), "+f"(c[2]), "+f"(c[3])
        : "r"(a[0]), "r"(a[1]), "r"(a[2]), "r"(a[3]), "r"(b[0]), "r"(b[1]));
}

// ---------------------------------------------------------------------------
// Kernel 1: QKV via HMMA bf16x3.  CTA tile 128(M) x 64(N), K chunks of 32.
// 8 warps: warp w -> (m-half w&1)*64, (n-quarter w>>1)*16.
// smem: A hi/lo [128][16]+pad uints (bf16x2 over k), W^T hi/lo [64][16]+pad.
// grid (12, 12, 3), 256 threads.
// ---------------------------------------------------------------------------
#define AP 18   // A row stride in uints
#define WP 20   // W^T row stride in uints (row byte stride 80 -> uint4 aligned)

__global__ __launch_bounds__(256)
void qkv_mma(const float* __restrict__ X,
             const float* __restrict__ Wq, const float* __restrict__ bq,
             const float* __restrict__ Wk, const float* __restrict__ bk,
             const float* __restrict__ Wv, const float* __restrict__ bv)
{
    __shared__ unsigned Ahi[128*AP], Alo[128*AP];
    __shared__ unsigned Bhi[64*WP],  Blo[64*WP];

    int z = blockIdx.z;
    const float* Wm = (z == 0) ? Wq : (z == 1) ? Wk : Wv;
    const float* bm = (z == 0) ? bq : (z == 1) ? bk : bv;

    int tid = threadIdx.x, w = tid >> 5, lane = tid & 31;
    int rowBase = blockIdx.y * 128;
    int colBase = blockIdx.x * 64;
    int mrow = (w & 1) * 64;      // warp m offset within CTA tile
    int ncol = (w >> 1) * 16;     // warp n offset

    int gr = lane >> 2, gq = lane & 3;

    float acc[4][2][4];
    #pragma unroll
    for (int mt = 0; mt < 4; mt++)
        #pragma unroll
        for (int nt = 0; nt < 2; nt++)
            #pragma unroll
            for (int i = 0; i < 4; i++) acc[mt][nt][i] = 0.f;

    for (int c = 0; c < 24; c++) {
        int kk = c * 32;
        __syncthreads();   // previous chunk's fragment reads complete

        // ---- X chunk [128 x 32] -> Ahi/Alo (bf16x2 pairs along k) ----
        {
            int r = tid >> 1, cb = (tid & 1) * 16;
            const float* xp = X + (size_t)(rowBase + r) * E + kk + cb;
            #pragma unroll
            for (int j = 0; j < 4; j++) {
                float4 x = *(const float4*)(xp + j * 4);
                unsigned short h0, h1, h2, h3, l0, l1, l2, l3;
                split_bf(x.x, h0, l0); split_bf(x.y, h1, l1);
                split_bf(x.z, h2, l2); split_bf(x.w, h3, l3);
                int pi = r * AP + (tid & 1) * 8 + j * 2;
                Ahi[pi]     = pk(h0, h1);
                Ahi[pi + 1] = pk(h2, h3);
                Alo[pi]     = pk(l0, l1);
                Alo[pi + 1] = pk(l2, l3);
            }
        }
        // ---- W chunk [32 x 64] -> W^T hi/lo [n][k-pairs] ----
        {
            int n = tid & 63, k0 = (tid >> 6) * 8;
            unsigned short hi[8], lo[8];
            #pragma unroll
            for (int j = 0; j < 8; j++)
                split_bf(Wm[(size_t)(kk + k0 + j) * E + colBase + n], hi[j], lo[j]);
            unsigned base = n * WP + (tid >> 6) * 4;
            *(uint4*)&Bhi[base] = make_uint4(pk(hi[0],hi[1]), pk(hi[2],hi[3]),
                                             pk(hi[4],hi[5]), pk(hi[6],hi[7]));
            *(uint4*)&Blo[base] = make_uint4(pk(lo[0],lo[1]), pk(lo[2],lo[3]),
                                             pk(lo[4],lo[5]), pk(lo[6],lo[7]));
        }
        __syncthreads();

        // ---- 2 x k16 MMA steps ----
        #pragma unroll
        for (int s = 0; s < 2; s++) {
            int pi = s * 8 + gq;
            unsigned afh[4][4], afl[4][4], bfh[2][2], bfl[2][2];
            #pragma unroll
            for (int mt = 0; mt < 4; mt++) {
                int rr = (mrow + mt * 16 + gr) * AP;
                afh[mt][0] = Ahi[rr + pi];
                afh[mt][1] = Ahi[rr + 8*AP + pi];
                afh[mt][2] = Ahi[rr + pi + 4];
                afh[mt][3] = Ahi[rr + 8*AP + pi + 4];
                afl[mt][0] = Alo[rr + pi];
                afl[mt][1] = Alo[rr + 8*AP + pi];
                afl[mt][2] = Alo[rr + pi + 4];
                afl[mt][3] = Alo[rr + 8*AP + pi + 4];
            }
            #pragma unroll
            for (int nt = 0; nt < 2; nt++) {
                int nn = (ncol + nt * 8 + gr) * WP;
                bfh[nt][0] = Bhi[nn + pi];
                bfh[nt][1] = Bhi[nn + pi + 4];
                bfl[nt][0] = Blo[nn + pi];
                bfl[nt][1] = Blo[nn + pi + 4];
            }
            #pragma unroll
            for (int mt = 0; mt < 4; mt++)
                #pragma unroll
                for (int nt = 0; nt < 2; nt++) {
                    mma_bf16(acc[mt][nt], afh[mt], bfh[nt]);
                    mma_bf16(acc[mt][nt], afh[mt], bfl[nt]);
                    mma_bf16(acc[mt][nt], afl[mt], bfh[nt]);
                }
        }
    }

    // ---- epilogue: c0,c1 -> row r, cols col..col+1; c2,c3 -> row r+8 ----
    #pragma unroll
    for (int nt = 0; nt < 2; nt++) {
        int col = colBase + ncol + nt * 8 + gq * 2;
        float b0 = bm[col], b1 = bm[col + 1];
        int h = col >> 6;
        int dd = (col >> 3) & 7;
        int s0 = col & 7;
        #pragma unroll
        for (int mt = 0; mt < 4; mt++) {
            int r0 = rowBase + mrow + mt * 16 + gr;
            #pragma unroll
            for (int half = 0; half < 2; half++) {
                int m = r0 + half * 8;
                int bb = m / L, l = m - bb * L;
                float2 v = make_float2(acc[mt][nt][half*2]     + b0,
                                       acc[mt][nt][half*2 + 1] + b1);
                if (z < 2) {
                    float* dst = (z == 0 ? g_Q : g_K)
                        + (((size_t)(bb * H + h) * D + dd) * L + l) * 8 + s0;
                    *(float2*)dst = v;
                } else {
                    float* dst = g_V + ((size_t)(bb * H + h) * L + l) * 64 + (col & 63);
                    *(float2*)dst = v;
                }
            }
        }
    }
}

// ---------------------------------------------------------------------------
// Kernel 2: stats pass (no-rescale softmax, log2-domain, raw ex2).
// grid: (SQT, D, BH), 256 threads; warp = 4 q rows.
// ---------------------------------------------------------------------------
__global__ __launch_bounds__(256)
void attn_stats(const float* __restrict__ mask)
{
    int bh = blockIdx.z, d = blockIdx.y, qt = blockIdx.x;
    int w = threadIdx.x >> 5, lane = threadIdx.x & 31;
    int b = bh / H;
    int q0 = qt * 32 + w * 4;

    const float* Kd = g_K + ((size_t)(bh * D + d) * L) * DS;
    const float* Qd = g_Q + ((size_t)(bh * D + d) * L) * DS;
    const float* mrow = mask + b * L;

    ull qp[4][4];
    #pragma unroll
    for (int r = 0; r < 4; r++) {
        const ulonglong2* qq = (const ulonglong2*)(Qd + (size_t)(q0 + r) * 8);
        ulonglong2 a = qq[0], bb2 = qq[1];
        qp[r][0] = a.x; qp[r][1] = a.y; qp[r][2] = bb2.x; qp[r][3] = bb2.y;
    }

    float Z[4] = {0,0,0,0}, S2[4] = {0,0,0,0}, ES[4] = {0,0,0,0}, EM[4] = {0,0,0,0};

    #pragma unroll 6
    for (int j = 0; j < 24; j++) {
        int k = j * 32 + lane;
        const ulonglong2* kp = (const ulonglong2*)(Kd + (size_t)k * 8);
        ulonglong2 kv0 = kp[0], kv1 = kp[1];
        float mk2 = __ldg(mrow + k) * LOG2E;
        #pragma unroll
        for (int r = 0; r < 4; r++) {
            ull t = ffma2(qp[r][0], kv0.x,
                    ffma2(qp[r][1], kv0.y,
                    ffma2(qp[r][2], kv1.x,
                    fmul2(qp[r][3], kv1.y))));
            float2 u = unpk(t);
            float s2l = fmaf(u.x + u.y, SCALE2, mk2);
            float e = ex2f(s2l);
            Z[r] += e;
            S2[r] = fmaf(e, e, S2[r]);
            ES[r] = fmaf(e, s2l, ES[r]);
            EM[r] = fmaxf(EM[r], e);
        }
    }

    #pragma unroll
    for (int r = 0; r < 4; r++) {
        #pragma unroll
        for (int o = 16; o; o >>= 1) {
            Z[r]  += __shfl_xor_sync(0xffffffffu, Z[r],  o);
            S2[r] += __shfl_xor_sync(0xffffffffu, S2[r], o);
            ES[r] += __shfl_xor_sync(0xffffffffu, ES[r], o);
            EM[r]  = fmaxf(EM[r], __shfl_xor_sync(0xffffffffu, EM[r], o));
        }
    }

    __shared__ float sH[8], sM[8], sE[8];
    if (lane == 0) {
        float hh = 0, mm = 0, ee = 0;
        #pragma unroll
        for (int r = 0; r < 4; r++) {
            float invZ = 1.f / Z[r];
            g_invZ[((size_t)(bh * D + d)) * L + q0 + r] = invZ;
            hh += S2[r] * invZ * invZ;
            mm += EM[r] * invZ;
            ee += __logf(Z[r]) - (ES[r] * invZ) * LN2;   // natural-log entropy
        }
        sH[w] = hh; sM[w] = mm; sE[w] = ee;
    }
    __syncthreads();
    if (threadIdx.x == 0) {
        float hh = 0, mm = 0, ee = 0;
        #pragma unroll
        for (int ww = 0; ww < 8; ww++) { hh += sH[ww]; mm += sM[ww]; ee += sE[ww]; }
        size_t idx = ((size_t)(bh * D + d) * SQT + qt) * 3;
        g_part[idx + 0] = hh;
        g_part[idx + 1] = mm;
        g_part[idx + 2] = ee;
    }
}

// ---------------------------------------------------------------------------
// Kernel 3: fused reduction (double) + min-max norm + depth softmax.
// ONE block, 512 threads; warp w -> (b = w>>3, d = w&7).
// ---------------------------------------------------------------------------
__global__ __launch_bounds__(512)
void stats_weights()
{
    int t = threadIdx.x, w = t >> 5, lane = t & 31;
    __shared__ float st[2][4][D];

    int b = w >> 3, d = w & 7;
    double s2 = 0, mx = 0, en = 0;
    for (int i = lane; i < H * SQT; i += 32) {
        int h = i / SQT, qt = i - (i / SQT) * SQT;
        size_t idx = ((size_t)((b * H + h) * D + d) * SQT + qt) * 3;
        s2 += (double)g_part[idx + 0];
        mx += (double)g_part[idx + 1];
        en += (double)g_part[idx + 2];
    }
    #pragma unroll
    for (int o = 16; o; o >>= 1) {
        s2 += __shfl_xor_sync(0xffffffffu, s2, o);
        mx += __shfl_xor_sync(0xffffffffu, mx, o);
        en += __shfl_xor_sync(0xffffffffu, en, o);
    }
    if (lane == 0) {
        double n = (double)H * (double)L;
        double S2m = s2 / n;
        st[b][0][d] = (float)((S2m - 1.0 / (double)L) / (double)(L - 1));
        st[b][1][d] = (float)(mx / n);
        st[b][2][d] = (float)(en / n);
        st[b][3][d] = (float)S2m;
    }
    __syncthreads();
    if (t < 2) {
        int bb = t;
        float nrm[4][D];
        for (int j = 0; j < 4; j++) {
            float mn = st[bb][j][0], mxv = st[bb][j][0];
            for (int dd = 1; dd < D; dd++) {
                mn = fminf(mn, st[bb][j][dd]); mxv = fmaxf(mxv, st[bb][j][dd]);
            }
            float den = fmaxf(mxv - mn, 1e-12f);
            for (int dd = 0; dd < D; dd++) nrm[j][dd] = (st[bb][j][dd] - mn) / den;
        }
        float sc[D], mxs = -1e30f;
        for (int dd = 0; dd < D; dd++) {
            sc[dd] = 2.5f * (0.5f * nrm[0][dd] + 0.3f * nrm[1][dd]
                             + 0.2f * nrm[3][dd] - 0.4f * nrm[2][dd]);
            mxs = fmaxf(mxs, sc[dd]);
        }
        float Z = 0.f, e[D];
        for (int dd = 0; dd < D; dd++) { e[dd] = expf(sc[dd] - mxs); Z += e[dd]; }
        for (int dd = 0; dd < D; dd++) g_w[bb * D + dd] = e[dd] / Z;
    }
}

// ---------------------------------------------------------------------------
// Kernel 4: combine pass -> attn4 (raw ex2, stored invZ, no reductions).
// grid: (CQT, BH), 256 threads.
// ---------------------------------------------------------------------------
__global__ __launch_bounds__(256)
void attn_combine(const float* __restrict__ mask, float* __restrict__ out_attn)
{
    int bh = blockIdx.y;
    int w = threadIdx.x >> 5, lane = threadIdx.x & 31;
    int b = bh / H;
    int q0 = blockIdx.x * 8;
    int kb = w * 96;
    const float* mrow = mask + b * L;

    __shared__ float sf[8][8];
    if (threadIdx.x < 64) {
        int r = threadIdx.x >> 3, d = threadIdx.x & 7;
        sf[r][d] = g_w[b * D + d] * g_invZ[((size_t)(bh * D + d)) * L + q0 + r];
    }
    __syncthreads();

    float mk2[3];
    #pragma unroll
    for (int j = 0; j < 3; j++) mk2[j] = __ldg(mrow + kb + j * 32 + lane) * LOG2E;

    float acc[8][3];
    #pragma unroll
    for (int r = 0; r < 8; r++)
        #pragma unroll
        for (int j = 0; j < 3; j++) acc[r][j] = 0.f;

    for (int d = 0; d < D; d++) {
        const float* Kd = g_K + ((size_t)(bh * D + d) * L) * DS;
        const float* Qd = g_Q + ((size_t)(bh * D + d) * L) * DS;
        ull qp[8][4];
        #pragma unroll
        for (int r = 0; r < 8; r++) {
            const ulonglong2* qq = (const ulonglong2*)(Qd + (size_t)(q0 + r) * 8);
            ulonglong2 a = qq[0], bb2 = qq[1];
            qp[r][0] = a.x; qp[r][1] = a.y; qp[r][2] = bb2.x; qp[r][3] = bb2.y;
        }
        float fr[8];
        #pragma unroll
        for (int r = 0; r < 8; r++) fr[r] = sf[r][d];

        #pragma unroll
        for (int j = 0; j < 3; j++) {
            int k = kb + j * 32 + lane;
            const ulonglong2* kp = (const ulonglong2*)(Kd + (size_t)k * 8);
            ulonglong2 kv0 = kp[0], kv1 = kp[1];
            #pragma unroll
            for (int r = 0; r < 8; r++) {
                ull t = ffma2(qp[r][0], kv0.x,
                        ffma2(qp[r][1], kv0.y,
                        ffma2(qp[r][2], kv1.x,
                        fmul2(qp[r][3], kv1.y))));
                float2 u = unpk(t);
                float e = ex2f(fmaf(u.x + u.y, SCALE2, mk2[j]));
                acc[r][j] = fmaf(e, fr[r], acc[r][j]);
            }
        }
    }

    #pragma unroll
    for (int r = 0; r < 8; r++) {
        float* row = out_attn + ((size_t)bh * L + q0 + r) * L;
        #pragma unroll
        for (int j = 0; j < 3; j++) row[kb + j * 32 + lane] = acc[r][j];
    }
}

// ---------------------------------------------------------------------------
// Kernel 5: ctx = attn4 @ V per (b,h), f32x2. Tile 128(M) x 64(N=DH).
// grid: (L/128, BH), 256 threads.
// ---------------------------------------------------------------------------
__global__ __launch_bounds__(256)
void ctx_gemm(const float* __restrict__ attn4, float* __restrict__ out)
{
    int bh = blockIdx.y;
    int b = bh / H, h = bh % H;
    int rowBase = blockIdx.x * 128;

    __shared__ float  As[16][132];
    __shared__ float2 Vs2[16][66];

    int tx = threadIdx.x & 15;
    int ty = threadIdx.x >> 4;
    int tid = threadIdx.x;

    const float* A  = attn4 + (size_t)bh * L * L;
    const float* Vp = g_V + (size_t)bh * L * DH;

    ull acc[4][4];
    #pragma unroll
    for (int i = 0; i < 4; i++)
        #pragma unroll
        for (int j = 0; j < 4; j++) acc[i][j] = 0ull;

    for (int kk = 0; kk < L; kk += 16) {
        __syncthreads();
        {
            int r = tid >> 1, kc = (tid & 1) * 8;
            const float* ap = A + (size_t)(rowBase + r) * L + kk + kc;
            float4 a0 = *(const float4*)ap;
            float4 a1 = *(const float4*)(ap + 4);
            As[kc + 0][r] = a0.x; As[kc + 1][r] = a0.y;
            As[kc + 2][r] = a0.z; As[kc + 3][r] = a0.w;
            As[kc + 4][r] = a1.x; As[kc + 5][r] = a1.y;
            As[kc + 6][r] = a1.z; As[kc + 7][r] = a1.w;

            int t = tid >> 4, n = (tid & 15) * 4;
            const float* vp = Vp + (size_t)(kk + t) * DH + n;
            float4 vv = *(const float4*)vp;
            Vs2[t][n + 0] = make_float2(vv.x, vv.x);
            Vs2[t][n + 1] = make_float2(vv.y, vv.y);
            Vs2[t][n + 2] = make_float2(vv.z, vv.z);
            Vs2[t][n + 3] = make_float2(vv.w, vv.w);
        }
        __syncthreads();
        #pragma unroll
        for (int t = 0; t < 16; t++) {
            ulonglong2 a0 = *(const ulonglong2*)&As[t][ty * 8];
            ulonglong2 a1 = *(const ulonglong2*)&As[t][ty * 8 + 4];
            ulonglong2 b0 = *(const ulonglong2*)&Vs2[t][tx * 4];
            ulonglong2 b1 = *(const ulonglong2*)&Vs2[t][tx * 4 + 2];
            ull ap2[4] = {a0.x, a0.y, a1.x, a1.y};
            ull bd[4]  = {b0.x, b0.y, b1.x, b1.y};
            #pragma unroll
            for (int ip = 0; ip < 4; ip++)
                #pragma unroll
                for (int j = 0; j < 4; j++)
                    acc[ip][j] = ffma2(ap2[ip], bd[j], acc[ip][j]);
        }
    }

    #pragma unroll
    for (int ip = 0; ip < 4; ip++) {
        int l0 = rowBase + ty * 8 + ip * 2;
        float2 p0 = unpk(acc[ip][0]), p1 = unpk(acc[ip][1]);
        float2 p2 = unpk(acc[ip][2]), p3 = unpk(acc[ip][3]);
        float4 r0 = make_float4(p0.x, p1.x, p2.x, p3.x);
        float4 r1 = make_float4(p0.y, p1.y, p2.y, p3.y);
        float* d0 = out + ((size_t)(b * L + l0)) * E + h * DH + tx * 4;
        float* d1 = out + ((size_t)(b * L + l0 + 1)) * E + h * DH + tx * 4;
        *(float4*)d0 = r0;
        *(float4*)d1 = r1;
    }
}

// ---------------------------------------------------------------------------
extern "C" void kernel_launch(void* const* d_in, const int* in_sizes, int n_in,
                              void* d_out, int out_size)
{
    const float* X    = (const float*)d_in[0];
    const float* mask = (const float*)d_in[1];
    const float* Wq   = (const float*)d_in[2];
    const float* bq   = (const float*)d_in[3];
    const float* Wk   = (const float*)d_in[4];
    const float* bk   = (const float*)d_in[5];
    const float* Wv   = (const float*)d_in[6];
    const float* bv   = (const float*)d_in[7];

    float* out   = (float*)d_out;
    float* ctx   = out;                          // [B, L, E]
    float* attn4 = out + (size_t)B * L * E;      // [B, H, L, L]

    qkv_mma<<<dim3(12, 12, 3), 256>>>(X, Wq, bq, Wk, bk, Wv, bv);
    attn_stats<<<dim3(SQT, D, BH), 256>>>(mask);
    stats_weights<<<1, 512>>>();
    attn_combine<<<dim3(CQT, BH), 256>>>(mask, attn4);
    ctx_gemm<<<dim3(L / 128, BH), 256>>>(attn4, ctx);
}

// round 13
// speedup vs baseline: 2.6716x; 1.2306x over previous
#include <cuda_runtime.h>
#include <cuda_bf16.h>
#include <math.h>

typedef unsigned long long ull;

#define B   2
#define L   768
#define H   12
#define DH  64
#define D   8
#define DS  8
#define E   768
#define BH  (B*H)

#define SQT 24            // stats q-tiles of 32 rows
#define NPART (BH*D*SQT)

#define SCALE2 0.51006972f     // (1/sqrt(8)) * log2(e)
#define LOG2E  1.4426950408889634f
#define LN2    0.6931471805599453f

__device__ float g_Q[BH*D*L*DS];
__device__ float g_K[BH*D*L*DS];
__device__ float g_V[BH*L*DH];
__device__ float g_invZ[BH*D*L];
__device__ float g_part[NPART*3];
__device__ float g_w[B*D];

// ---------------- f32x2 + math helpers ----------------
__device__ __forceinline__ ull ffma2(ull a, ull b, ull c) {
    ull d_; asm("fma.rn.f32x2 %0, %1, %2, %3;" : "=l"(d_) : "l"(a), "l"(b), "l"(c));
    return d_;
}
__device__ __forceinline__ ull fmul2(ull a, ull b) {
    ull d_; asm("mul.rn.f32x2 %0, %1, %2;" : "=l"(d_) : "l"(a), "l"(b));
    return d_;
}
__device__ __forceinline__ float2 unpk(ull v) {
    float2 f; asm("mov.b64 {%0, %1}, %2;" : "=f"(f.x), "=f"(f.y) : "l"(v));
    return f;
}
__device__ __forceinline__ float ex2f(float x) {
    float r; asm("ex2.approx.ftz.f32 %0, %1;" : "=f"(r) : "f"(x));
    return r;
}

// ---------------- bf16 split/pack + mma.sync ----------------
__device__ __forceinline__ void split_bf(float x, unsigned short& hi, unsigned short& lo) {
    __nv_bfloat16 h = __float2bfloat16_rn(x);
    hi = __bfloat16_as_ushort(h);
    lo = __bfloat16_as_ushort(__float2bfloat16_rn(x - __bfloat162float(h)));
}
__device__ __forceinline__ unsigned pk(unsigned short a, unsigned short b) {
    return (unsigned)a | ((unsigned)b << 16);
}
// k16 variant (qkv GEMM)
__device__ __forceinline__ void mma_bf16(float* c, const unsigned* a, const unsigned* b) {
    asm volatile(
        "mma.sync.aligned.m16n8k16.row.col.f32.bf16.bf16.f32 "
        "{%0,%1,%2,%3}, {%4,%5,%6,%7}, {%8,%9}, {%0,%1,%2,%3};"
        : "+f"(c[0]), "+f"(c[1]), "+f"(c[2]), "+f"(c[3])
        : "r"(a[0]), "r"(a[1]), "r"(a[2]), "r"(a[3]), "r"(b[0]), "r"(b[1]));
}
// k8 variant (attention scores: k = DS = 8)
__device__ __forceinline__ void mma_k8(float* c, const unsigned* a, unsigned b) {
    asm volatile(
        "mma.sync.aligned.m16n8k8.row.col.f32.bf16.bf16.f32 "
        "{%0,%1,%2,%3}, {%4,%5}, {%6}, {%0,%1,%2,%3};"
        : "+f"(c[0]), "+f"(c[1]), "+f"(c[2]), "+f"(c[3])
        : "r"(a[0]), "r"(a[1]), "r"(b));
}
// split a float2 into packed bf16x2 hi/lo
__device__ __forceinline__ void split2(float2 v, unsigned& hi, unsigned& lo) {
    unsigned short h0, l0, h1, l1;
    split_bf(v.x, h0, l0); split_bf(v.y, h1, l1);
    hi = pk(h0, h1); lo = pk(l0, l1);
}

// ---------------------------------------------------------------------------
// Kernel 1: QKV via HMMA bf16x3 (unchanged from R10 win).
// ---------------------------------------------------------------------------
#define AP 18
#define WP 20

__global__ __launch_bounds__(256)
void qkv_mma(const float* __restrict__ X,
             const float* __restrict__ Wq, const float* __restrict__ bq,
             const float* __restrict__ Wk, const float* __restrict__ bk,
             const float* __restrict__ Wv, const float* __restrict__ bv)
{
    __shared__ unsigned Ahi[128*AP], Alo[128*AP];
    __shared__ unsigned Bhi[64*WP],  Blo[64*WP];

    int z = blockIdx.z;
    const float* Wm = (z == 0) ? Wq : (z == 1) ? Wk : Wv;
    const float* bm = (z == 0) ? bq : (z == 1) ? bk : bv;

    int tid = threadIdx.x, w = tid >> 5, lane = tid & 31;
    int rowBase = blockIdx.y * 128;
    int colBase = blockIdx.x * 64;
    int mrow = (w & 1) * 64;
    int ncol = (w >> 1) * 16;

    int gr = lane >> 2, gq = lane & 3;

    float acc[4][2][4];
    #pragma unroll
    for (int mt = 0; mt < 4; mt++)
        #pragma unroll
        for (int nt = 0; nt < 2; nt++)
            #pragma unroll
            for (int i = 0; i < 4; i++) acc[mt][nt][i] = 0.f;

    for (int c = 0; c < 24; c++) {
        int kk = c * 32;
        __syncthreads();

        {
            int r = tid >> 1, cb = (tid & 1) * 16;
            const float* xp = X + (size_t)(rowBase + r) * E + kk + cb;
            #pragma unroll
            for (int j = 0; j < 4; j++) {
                float4 x = *(const float4*)(xp + j * 4);
                unsigned short h0, h1, h2, h3, l0, l1, l2, l3;
                split_bf(x.x, h0, l0); split_bf(x.y, h1, l1);
                split_bf(x.z, h2, l2); split_bf(x.w, h3, l3);
                int pi = r * AP + (tid & 1) * 8 + j * 2;
                Ahi[pi]     = pk(h0, h1);
                Ahi[pi + 1] = pk(h2, h3);
                Alo[pi]     = pk(l0, l1);
                Alo[pi + 1] = pk(l2, l3);
            }
        }
        {
            int n = tid & 63, k0 = (tid >> 6) * 8;
            unsigned short hi[8], lo[8];
            #pragma unroll
            for (int j = 0; j < 8; j++)
                split_bf(Wm[(size_t)(kk + k0 + j) * E + colBase + n], hi[j], lo[j]);
            unsigned base = n * WP + (tid >> 6) * 4;
            *(uint4*)&Bhi[base] = make_uint4(pk(hi[0],hi[1]), pk(hi[2],hi[3]),
                                             pk(hi[4],hi[5]), pk(hi[6],hi[7]));
            *(uint4*)&Blo[base] = make_uint4(pk(lo[0],lo[1]), pk(lo[2],lo[3]),
                                             pk(lo[4],lo[5]), pk(lo[6],lo[7]));
        }
        __syncthreads();

        #pragma unroll
        for (int s = 0; s < 2; s++) {
            int pi = s * 8 + gq;
            unsigned afh[4][4], afl[4][4], bfh[2][2], bfl[2][2];
            #pragma unroll
            for (int mt = 0; mt < 4; mt++) {
                int rr = (mrow + mt * 16 + gr) * AP;
                afh[mt][0] = Ahi[rr + pi];
                afh[mt][1] = Ahi[rr + 8*AP + pi];
                afh[mt][2] = Ahi[rr + pi + 4];
                afh[mt][3] = Ahi[rr + 8*AP + pi + 4];
                afl[mt][0] = Alo[rr + pi];
                afl[mt][1] = Alo[rr + 8*AP + pi];
                afl[mt][2] = Alo[rr + pi + 4];
                afl[mt][3] = Alo[rr + 8*AP + pi + 4];
            }
            #pragma unroll
            for (int nt = 0; nt < 2; nt++) {
                int nn = (ncol + nt * 8 + gr) * WP;
                bfh[nt][0] = Bhi[nn + pi];
                bfh[nt][1] = Bhi[nn + pi + 4];
                bfl[nt][0] = Blo[nn + pi];
                bfl[nt][1] = Blo[nn + pi + 4];
            }
            #pragma unroll
            for (int mt = 0; mt < 4; mt++)
                #pragma unroll
                for (int nt = 0; nt < 2; nt++) {
                    mma_bf16(acc[mt][nt], afh[mt], bfh[nt]);
                    mma_bf16(acc[mt][nt], afh[mt], bfl[nt]);
                    mma_bf16(acc[mt][nt], afl[mt], bfh[nt]);
                }
        }
    }

    #pragma unroll
    for (int nt = 0; nt < 2; nt++) {
        int col = colBase + ncol + nt * 8 + gq * 2;
        float b0 = bm[col], b1 = bm[col + 1];
        int h = col >> 6;
        int dd = (col >> 3) & 7;
        int s0 = col & 7;
        #pragma unroll
        for (int mt = 0; mt < 4; mt++) {
            int r0 = rowBase + mrow + mt * 16 + gr;
            #pragma unroll
            for (int half = 0; half < 2; half++) {
                int m = r0 + half * 8;
                int bb = m / L, l = m - bb * L;
                float2 v = make_float2(acc[mt][nt][half*2]     + b0,
                                       acc[mt][nt][half*2 + 1] + b1);
                if (z < 2) {
                    float* dst = (z == 0 ? g_Q : g_K)
                        + (((size_t)(bb * H + h) * D + dd) * L + l) * 8 + s0;
                    *(float2*)dst = v;
                } else {
                    float* dst = g_V + ((size_t)(bb * H + h) * L + l) * 64 + (col & 63);
                    *(float2*)dst = v;
                }
            }
        }
    }
}

// ---------------------------------------------------------------------------
// Kernel 2: stats pass via HMMA m16n8k8 bf16x3 scores.
// CTA = (bh, d, qt): 32 q rows x full K=768.
// 8 warps: mhalf=(w&1)*16, k-range (w>>1)*192 (24 n-tiles of 8).
// Fragments load straight from global (A: Q row float2; B: K row float2).
// grid: (SQT, D, BH), 256 threads.
// ---------------------------------------------------------------------------
__global__ __launch_bounds__(256)
void attn_stats(const float* __restrict__ mask)
{
    __shared__ float sZ[4][32], sS2[4][32], sES[4][32], sEM[4][32];

    int bh = blockIdx.z, d = blockIdx.y, qt = blockIdx.x;
    int tid = threadIdx.x, w = tid >> 5, lane = tid & 31;
    int gr = lane >> 2, gq = lane & 3;
    int b = bh / H;
    int q0 = qt * 32;
    int mhalf = (w & 1) * 16;
    int kpart = w >> 1;            // 0..3, each 192 k
    int kb = kpart * 192;

    const float* Kd = g_K + ((size_t)(bh * D + d) * L) * DS;
    const float* Qd = g_Q + ((size_t)(bh * D + d) * L) * DS;
    const float* mrow = mask + b * L;

    // A fragment: rows q0+mhalf+gr, +8; dims 2gq, 2gq+1
    unsigned ahi[2], alo[2];
    split2(*(const float2*)(Qd + (size_t)(q0 + mhalf + gr) * 8 + 2 * gq), ahi[0], alo[0]);
    split2(*(const float2*)(Qd + (size_t)(q0 + mhalf + gr + 8) * 8 + 2 * gq), ahi[1], alo[1]);

    float Zs[2] = {0, 0}, S2s[2] = {0, 0}, ESs[2] = {0, 0}, EMs[2] = {0, 0};

    #pragma unroll 4
    for (int nt = 0; nt < 24; nt++) {
        int krow = kb + nt * 8 + gr;
        unsigned bhi, blo;
        split2(*(const float2*)(Kd + (size_t)krow * 8 + 2 * gq), bhi, blo);

        float c[4] = {0.f, 0.f, 0.f, 0.f};
        mma_k8(c, ahi, bhi);
        mma_k8(c, ahi, blo);
        mma_k8(c, alo, bhi);

        float2 m2 = *(const float2*)(mrow + kb + nt * 8 + 2 * gq);
        float mk0 = m2.x * LOG2E, mk1 = m2.y * LOG2E;

        #pragma unroll
        for (int i = 0; i < 4; i++) {
            float s2l = fmaf(c[i], SCALE2, (i & 1) ? mk1 : mk0);
            float e = ex2f(s2l);
            int r = i >> 1;
            Zs[r] += e;
            S2s[r] = fmaf(e, e, S2s[r]);
            ESs[r] = fmaf(e, s2l, ESs[r]);
            EMs[r] = fmaxf(EMs[r], e);
        }
    }

    // reduce over quad lanes (cols)
    #pragma unroll
    for (int r = 0; r < 2; r++) {
        #pragma unroll
        for (int o = 1; o <= 2; o <<= 1) {
            Zs[r]  += __shfl_xor_sync(0xffffffffu, Zs[r],  o);
            S2s[r] += __shfl_xor_sync(0xffffffffu, S2s[r], o);
            ESs[r] += __shfl_xor_sync(0xffffffffu, ESs[r], o);
            EMs[r]  = fmaxf(EMs[r], __shfl_xor_sync(0xffffffffu, EMs[r], o));
        }
    }
    if (gq == 0) {
        #pragma unroll
        for (int r = 0; r < 2; r++) {
            int row = mhalf + gr + r * 8;
            sZ[kpart][row]  = Zs[r];
            sS2[kpart][row] = S2s[r];
            sES[kpart][row] = ESs[r];
            sEM[kpart][row] = EMs[r];
        }
    }
    __syncthreads();

    if (tid < 32) {
        int row = tid;
        float Z = 0, S2 = 0, ES = 0, EM = 0;
        #pragma unroll
        for (int j = 0; j < 4; j++) {
            Z += sZ[j][row]; S2 += sS2[j][row]; ES += sES[j][row];
            EM = fmaxf(EM, sEM[j][row]);
        }
        float invZ = 1.f / Z;
        g_invZ[((size_t)(bh * D + d)) * L + q0 + row] = invZ;
        float hh = S2 * invZ * invZ;
        float mm = EM * invZ;
        float ee = __logf(Z) - (ES * invZ) * LN2;
        #pragma unroll
        for (int o = 16; o; o >>= 1) {
            hh += __shfl_xor_sync(0xffffffffu, hh, o);
            mm += __shfl_xor_sync(0xffffffffu, mm, o);
            ee += __shfl_xor_sync(0xffffffffu, ee, o);
        }
        if (tid == 0) {
            size_t idx = ((size_t)(bh * D + d) * SQT + qt) * 3;
            g_part[idx + 0] = hh;
            g_part[idx + 1] = mm;
            g_part[idx + 2] = ee;
        }
    }
}

// ---------------------------------------------------------------------------
// Kernel 3: fused reduction (double) + min-max norm + depth softmax (1 block).
// ---------------------------------------------------------------------------
__global__ __launch_bounds__(512)
void stats_weights()
{
    int t = threadIdx.x, w = t >> 5, lane = t & 31;
    __shared__ float st[2][4][D];

    int b = w >> 3, d = w & 7;
    double s2 = 0, mx = 0, en = 0;
    for (int i = lane; i < H * SQT; i += 32) {
        int h = i / SQT, qt = i - (i / SQT) * SQT;
        size_t idx = ((size_t)((b * H + h) * D + d) * SQT + qt) * 3;
        s2 += (double)g_part[idx + 0];
        mx += (double)g_part[idx + 1];
        en += (double)g_part[idx + 2];
    }
    #pragma unroll
    for (int o = 16; o; o >>= 1) {
        s2 += __shfl_xor_sync(0xffffffffu, s2, o);
        mx += __shfl_xor_sync(0xffffffffu, mx, o);
        en += __shfl_xor_sync(0xffffffffu, en, o);
    }
    if (lane == 0) {
        double n = (double)H * (double)L;
        double S2m = s2 / n;
        st[b][0][d] = (float)((S2m - 1.0 / (double)L) / (double)(L - 1));
        st[b][1][d] = (float)(mx / n);
        st[b][2][d] = (float)(en / n);
        st[b][3][d] = (float)S2m;
    }
    __syncthreads();
    if (t < 2) {
        int bb = t;
        float nrm[4][D];
        for (int j = 0; j < 4; j++) {
            float mn = st[bb][j][0], mxv = st[bb][j][0];
            for (int dd = 1; dd < D; dd++) {
                mn = fminf(mn, st[bb][j][dd]); mxv = fmaxf(mxv, st[bb][j][dd]);
            }
            float den = fmaxf(mxv - mn, 1e-12f);
            for (int dd = 0; dd < D; dd++) nrm[j][dd] = (st[bb][j][dd] - mn) / den;
        }
        float sc[D], mxs = -1e30f;
        for (int dd = 0; dd < D; dd++) {
            sc[dd] = 2.5f * (0.5f * nrm[0][dd] + 0.3f * nrm[1][dd]
                             + 0.2f * nrm[3][dd] - 0.4f * nrm[2][dd]);
            mxs = fmaxf(mxs, sc[dd]);
        }
        float Z = 0.f, e[D];
        for (int dd = 0; dd < D; dd++) { e[dd] = expf(sc[dd] - mxs); Z += e[dd]; }
        for (int dd = 0; dd < D; dd++) g_w[bb * D + dd] = e[dd] / Z;
    }
}

// ---------------------------------------------------------------------------
// Kernel 4: combine pass via HMMA m16n8k8 bf16x3 scores -> attn4.
// CTA = (qt 32 rows, kr 256 cols, bh).  8 warps: mhalf=(w&1)*16,
// n-range (w>>1)*64 (8 n-tiles).  acc[8][4] persists across d.
// grid: (24, 3, BH), 256 threads.
// ---------------------------------------------------------------------------
__global__ __launch_bounds__(256)
void attn_combine(const float* __restrict__ mask, float* __restrict__ out_attn)
{
    __shared__ float sf[32][8];   // [row][d] = w_d * invZ

    int qt = blockIdx.x, kr = blockIdx.y, bh = blockIdx.z;
    int tid = threadIdx.x, w = tid >> 5, lane = tid & 31;
    int gr = lane >> 2, gq = lane & 3;
    int b = bh / H;
    int q0 = qt * 32;
    int mhalf = (w & 1) * 16;
    int kb = kr * 256 + (w >> 1) * 64;
    const float* mrow = mask + b * L;

    {   // 256 threads = 32 rows x 8 depths exactly
        int r = tid >> 3, dd = tid & 7;
        sf[r][dd] = g_w[b * D + dd] *
                    g_invZ[((size_t)(bh * D + dd)) * L + q0 + r];
    }
    __syncthreads();

    float mkv[8][2];
    #pragma unroll
    for (int nt = 0; nt < 8; nt++) {
        float2 m2 = *(const float2*)(mrow + kb + nt * 8 + 2 * gq);
        mkv[nt][0] = m2.x * LOG2E;
        mkv[nt][1] = m2.y * LOG2E;
    }

    float acc[8][4];
    #pragma unroll
    for (int nt = 0; nt < 8; nt++)
        #pragma unroll
        for (int i = 0; i < 4; i++) acc[nt][i] = 0.f;

    for (int d = 0; d < D; d++) {
        const float* Kd = g_K + ((size_t)(bh * D + d) * L) * DS;
        const float* Qd = g_Q + ((size_t)(bh * D + d) * L) * DS;

        unsigned ahi[2], alo[2];
        split2(*(const float2*)(Qd + (size_t)(q0 + mhalf + gr) * 8 + 2 * gq), ahi[0], alo[0]);
        split2(*(const float2*)(Qd + (size_t)(q0 + mhalf + gr + 8) * 8 + 2 * gq), ahi[1], alo[1]);

        float fr0 = sf[mhalf + gr][d];
        float fr1 = sf[mhalf + gr + 8][d];

        #pragma unroll
        for (int nt = 0; nt < 8; nt++) {
            int krow = kb + nt * 8 + gr;
            unsigned bhi, blo;
            split2(*(const float2*)(Kd + (size_t)krow * 8 + 2 * gq), bhi, blo);

            float c[4] = {0.f, 0.f, 0.f, 0.f};
            mma_k8(c, ahi, bhi);
            mma_k8(c, ahi, blo);
            mma_k8(c, alo, bhi);

            #pragma unroll
            for (int i = 0; i < 4; i++) {
                float e = ex2f(fmaf(c[i], SCALE2, mkv[nt][i & 1]));
                acc[nt][i] = fmaf(e, (i >> 1) ? fr1 : fr0, acc[nt][i]);
            }
        }
    }

    int row0 = q0 + mhalf + gr;
    #pragma unroll
    for (int nt = 0; nt < 8; nt++) {
        int col = kb + nt * 8 + 2 * gq;
        *(float2*)(out_attn + ((size_t)bh * L + row0) * L + col) =
            make_float2(acc[nt][0], acc[nt][1]);
        *(float2*)(out_attn + ((size_t)bh * L + row0 + 8) * L + col) =
            make_float2(acc[nt][2], acc[nt][3]);
    }
}

// ---------------------------------------------------------------------------
// Kernel 5: ctx = attn4 @ V per (b,h), f32x2 (unchanged).
// ---------------------------------------------------------------------------
__global__ __launch_bounds__(256)
void ctx_gemm(const float* __restrict__ attn4, float* __restrict__ out)
{
    int bh = blockIdx.y;
    int b = bh / H, h = bh % H;
    int rowBase = blockIdx.x * 128;

    __shared__ float  As[16][132];
    __shared__ float2 Vs2[16][66];

    int tx = threadIdx.x & 15;
    int ty = threadIdx.x >> 4;
    int tid = threadIdx.x;

    const float* A  = attn4 + (size_t)bh * L * L;
    const float* Vp = g_V + (size_t)bh * L * DH;

    ull acc[4][4];
    #pragma unroll
    for (int i = 0; i < 4; i++)
        #pragma unroll
        for (int j = 0; j < 4; j++) acc[i][j] = 0ull;

    for (int kk = 0; kk < L; kk += 16) {
        __syncthreads();
        {
            int r = tid >> 1, kc = (tid & 1) * 8;
            const float* ap = A + (size_t)(rowBase + r) * L + kk + kc;
            float4 a0 = *(const float4*)ap;
            float4 a1 = *(const float4*)(ap + 4);
            As[kc + 0][r] = a0.x; As[kc + 1][r] = a0.y;
            As[kc + 2][r] = a0.z; As[kc + 3][r] = a0.w;
            As[kc + 4][r] = a1.x; As[kc + 5][r] = a1.y;
            As[kc + 6][r] = a1.z; As[kc + 7][r] = a1.w;

            int t = tid >> 4, n = (tid & 15) * 4;
            const float* vp = Vp + (size_t)(kk + t) * DH + n;
            float4 vv = *(const float4*)vp;
            Vs2[t][n + 0] = make_float2(vv.x, vv.x);
            Vs2[t][n + 1] = make_float2(vv.y, vv.y);
            Vs2[t][n + 2] = make_float2(vv.z, vv.z);
            Vs2[t][n + 3] = make_float2(vv.w, vv.w);
        }
        __syncthreads();
        #pragma unroll
        for (int t = 0; t < 16; t++) {
            ulonglong2 a0 = *(const ulonglong2*)&As[t][ty * 8];
            ulonglong2 a1 = *(const ulonglong2*)&As[t][ty * 8 + 4];
            ulonglong2 b0 = *(const ulonglong2*)&Vs2[t][tx * 4];
            ulonglong2 b1 = *(const ulonglong2*)&Vs2[t][tx * 4 + 2];
            ull ap2[4] = {a0.x, a0.y, a1.x, a1.y};
            ull bd[4]  = {b0.x, b0.y, b1.x, b1.y};
            #pragma unroll
            for (int ip = 0; ip < 4; ip++)
                #pragma unroll
                for (int j = 0; j < 4; j++)
                    acc[ip][j] = ffma2(ap2[ip], bd[j], acc[ip][j]);
        }
    }

    #pragma unroll
    for (int ip = 0; ip < 4; ip++) {
        int l0 = rowBase + ty * 8 + ip * 2;
        float2 p0 = unpk(acc[ip][0]), p1 = unpk(acc[ip][1]);
        float2 p2 = unpk(acc[ip][2]), p3 = unpk(acc[ip][3]);
        float4 r0 = make_float4(p0.x, p1.x, p2.x, p3.x);
        float4 r1 = make_float4(p0.y, p1.y, p2.y, p3.y);
        float* d0 = out + ((size_t)(b * L + l0)) * E + h * DH + tx * 4;
        float* d1 = out + ((size_t)(b * L + l0 + 1)) * E + h * DH + tx * 4;
        *(float4*)d0 = r0;
        *(float4*)d1 = r1;
    }
}

// ---------------------------------------------------------------------------
extern "C" void kernel_launch(void* const* d_in, const int* in_sizes, int n_in,
                              void* d_out, int out_size)
{
    const float* X    = (const float*)d_in[0];
    const float* mask = (const float*)d_in[1];
    const float* Wq   = (const float*)d_in[2];
    const float* bq   = (const float*)d_in[3];
    const float* Wk   = (const float*)d_in[4];
    const float* bk   = (const float*)d_in[5];
    const float* Wv   = (const float*)d_in[6];
    const float* bv   = (const float*)d_in[7];

    float* out   = (float*)d_out;
    float* ctx   = out;                          // [B, L, E]
    float* attn4 = out + (size_t)B * L * E;      // [B, H, L, L]

    qkv_mma<<<dim3(12, 12, 3), 256>>>(X, Wq, bq, Wk, bk, Wv, bv);
    attn_stats<<<dim3(SQT, D, BH), 256>>>(mask);
    stats_weights<<<1, 512>>>();
    attn_combine<<<dim3(24, 3, BH), 256>>>(mask, attn4);
    ctx_gemm<<<dim3(L / 128, BH), 256>>>(attn4, ctx);
}

// round 14
// speedup vs baseline: 3.2983x; 1.2346x over previous
#include <cuda_runtime.h>
#include <cuda_bf16.h>
#include <math.h>

typedef unsigned long long ull;

#define B   2
#define L   768
#define H   12
#define DH  64
#define D   8
#define DS  8
#define E   768
#define BH  (B*H)

#define SQT 24            // stats q-tiles of 32 rows
#define NPART (BH*D*SQT)

#define SCALE2 0.51006972f     // (1/sqrt(8)) * log2(e)
#define LOG2E  1.4426950408889634f
#define LN2    0.6931471805599453f

// Q/K stored pre-split: uint2{hi,lo} packed bf16x2 per 2 dims.
// index: ((bh*D + d)*L + l)*4 + pair   (pair = dim/2)
__device__ uint2 g_QP[BH*D*L*4];
__device__ uint2 g_KP[BH*D*L*4];
__device__ float g_V[BH*L*DH];
__device__ float g_invZ[BH*D*L];
__device__ float g_part[NPART*3];
__device__ float g_w[B*D];

// ---------------- math helpers ----------------
__device__ __forceinline__ float ex2f(float x) {
    float r; asm("ex2.approx.ftz.f32 %0, %1;" : "=f"(r) : "f"(x));
    return r;
}

// ---------------- bf16 split/pack + mma.sync ----------------
__device__ __forceinline__ void split_bf(float x, unsigned short& hi, unsigned short& lo) {
    __nv_bfloat16 h = __float2bfloat16_rn(x);
    hi = __bfloat16_as_ushort(h);
    lo = __bfloat16_as_ushort(__float2bfloat16_rn(x - __bfloat162float(h)));
}
__device__ __forceinline__ unsigned pk(unsigned short a, unsigned short b) {
    return (unsigned)a | ((unsigned)b << 16);
}
__device__ __forceinline__ void mma_bf16(float* c, const unsigned* a, const unsigned* b) {
    asm volatile(
        "mma.sync.aligned.m16n8k16.row.col.f32.bf16.bf16.f32 "
        "{%0,%1,%2,%3}, {%4,%5,%6,%7}, {%8,%9}, {%0,%1,%2,%3};"
        : "+f"(c[0]), "+f"(c[1]), "+f"(c[2]), "+f"(c[3])
        : "r"(a[0]), "r"(a[1]), "r"(a[2]), "r"(a[3]), "r"(b[0]), "r"(b[1]));
}
__device__ __forceinline__ void mma_k8(float* c, const unsigned* a, unsigned b) {
    asm volatile(
        "mma.sync.aligned.m16n8k8.row.col.f32.bf16.bf16.f32 "
        "{%0,%1,%2,%3}, {%4,%5}, {%6}, {%0,%1,%2,%3};"
        : "+f"(c[0]), "+f"(c[1]), "+f"(c[2]), "+f"(c[3])
        : "r"(a[0]), "r"(a[1]), "r"(b));
}

// ---------------------------------------------------------------------------
// Kernel 1: QKV via HMMA bf16x3.  Q/K epilogue stores pre-split planes.
// ---------------------------------------------------------------------------
#define AP 18
#define WP 20

__global__ __launch_bounds__(256)
void qkv_mma(const float* __restrict__ X,
             const float* __restrict__ Wq, const float* __restrict__ bq,
             const float* __restrict__ Wk, const float* __restrict__ bk,
             const float* __restrict__ Wv, const float* __restrict__ bv)
{
    __shared__ unsigned Ahi[128*AP], Alo[128*AP];
    __shared__ unsigned Bhi[64*WP],  Blo[64*WP];

    int z = blockIdx.z;
    const float* Wm = (z == 0) ? Wq : (z == 1) ? Wk : Wv;
    const float* bm = (z == 0) ? bq : (z == 1) ? bk : bv;

    int tid = threadIdx.x, w = tid >> 5, lane = tid & 31;
    int rowBase = blockIdx.y * 128;
    int colBase = blockIdx.x * 64;
    int mrow = (w & 1) * 64;
    int ncol = (w >> 1) * 16;

    int gr = lane >> 2, gq = lane & 3;

    float acc[4][2][4];
    #pragma unroll
    for (int mt = 0; mt < 4; mt++)
        #pragma unroll
        for (int nt = 0; nt < 2; nt++)
            #pragma unroll
            for (int i = 0; i < 4; i++) acc[mt][nt][i] = 0.f;

    for (int c = 0; c < 24; c++) {
        int kk = c * 32;
        __syncthreads();

        {
            int r = tid >> 1, cb = (tid & 1) * 16;
            const float* xp = X + (size_t)(rowBase + r) * E + kk + cb;
            #pragma unroll
            for (int j = 0; j < 4; j++) {
                float4 x = *(const float4*)(xp + j * 4);
                unsigned short h0, h1, h2, h3, l0, l1, l2, l3;
                split_bf(x.x, h0, l0); split_bf(x.y, h1, l1);
                split_bf(x.z, h2, l2); split_bf(x.w, h3, l3);
                int pi = r * AP + (tid & 1) * 8 + j * 2;
                Ahi[pi]     = pk(h0, h1);
                Ahi[pi + 1] = pk(h2, h3);
                Alo[pi]     = pk(l0, l1);
                Alo[pi + 1] = pk(l2, l3);
            }
        }
        {
            int n = tid & 63, k0 = (tid >> 6) * 8;
            unsigned short hi[8], lo[8];
            #pragma unroll
            for (int j = 0; j < 8; j++)
                split_bf(Wm[(size_t)(kk + k0 + j) * E + colBase + n], hi[j], lo[j]);
            unsigned base = n * WP + (tid >> 6) * 4;
            *(uint4*)&Bhi[base] = make_uint4(pk(hi[0],hi[1]), pk(hi[2],hi[3]),
                                             pk(hi[4],hi[5]), pk(hi[6],hi[7]));
            *(uint4*)&Blo[base] = make_uint4(pk(lo[0],lo[1]), pk(lo[2],lo[3]),
                                             pk(lo[4],lo[5]), pk(lo[6],lo[7]));
        }
        __syncthreads();

        #pragma unroll
        for (int s = 0; s < 2; s++) {
            int pi = s * 8 + gq;
            unsigned afh[4][4], afl[4][4], bfh[2][2], bfl[2][2];
            #pragma unroll
            for (int mt = 0; mt < 4; mt++) {
                int rr = (mrow + mt * 16 + gr) * AP;
                afh[mt][0] = Ahi[rr + pi];
                afh[mt][1] = Ahi[rr + 8*AP + pi];
                afh[mt][2] = Ahi[rr + pi + 4];
                afh[mt][3] = Ahi[rr + 8*AP + pi + 4];
                afl[mt][0] = Alo[rr + pi];
                afl[mt][1] = Alo[rr + 8*AP + pi];
                afl[mt][2] = Alo[rr + pi + 4];
                afl[mt][3] = Alo[rr + 8*AP + pi + 4];
            }
            #pragma unroll
            for (int nt = 0; nt < 2; nt++) {
                int nn = (ncol + nt * 8 + gr) * WP;
                bfh[nt][0] = Bhi[nn + pi];
                bfh[nt][1] = Bhi[nn + pi + 4];
                bfl[nt][0] = Blo[nn + pi];
                bfl[nt][1] = Blo[nn + pi + 4];
            }
            #pragma unroll
            for (int mt = 0; mt < 4; mt++)
                #pragma unroll
                for (int nt = 0; nt < 2; nt++) {
                    mma_bf16(acc[mt][nt], afh[mt], bfh[nt]);
                    mma_bf16(acc[mt][nt], afh[mt], bfl[nt]);
                    mma_bf16(acc[mt][nt], afl[mt], bfh[nt]);
                }
        }
    }

    #pragma unroll
    for (int nt = 0; nt < 2; nt++) {
        int col = colBase + ncol + nt * 8 + gq * 2;
        float b0 = bm[col], b1 = bm[col + 1];
        int h = col >> 6;
        int dd = (col >> 3) & 7;
        int pair = (col >> 1) & 3;
        #pragma unroll
        for (int mt = 0; mt < 4; mt++) {
            int r0 = rowBase + mrow + mt * 16 + gr;
            #pragma unroll
            for (int half = 0; half < 2; half++) {
                int m = r0 + half * 8;
                int bb = m / L, l = m - bb * L;
                float v0 = acc[mt][nt][half*2]     + b0;
                float v1 = acc[mt][nt][half*2 + 1] + b1;
                if (z < 2) {
                    unsigned short h0, l0, h1, l1;
                    split_bf(v0, h0, l0); split_bf(v1, h1, l1);
                    uint2* dst = (z == 0 ? g_QP : g_KP)
                        + (((size_t)(bb * H + h) * D + dd) * L + l) * 4 + pair;
                    *dst = make_uint2(pk(h0, h1), pk(l0, l1));
                } else {
                    float* dst = g_V + ((size_t)(bb * H + h) * L + l) * 64 + (col & 63);
                    *(float2*)dst = make_float2(v0, v1);
                }
            }
        }
    }
}

// ---------------------------------------------------------------------------
// Kernel 2: stats pass via HMMA m16n8k8, fragments direct from packed planes.
// grid: (SQT, D, BH), 256 threads.
// ---------------------------------------------------------------------------
__global__ __launch_bounds__(256)
void attn_stats(const float* __restrict__ mask)
{
    __shared__ float sZ[4][32], sS2[4][32], sES[4][32], sEM[4][32];

    int bh = blockIdx.z, d = blockIdx.y, qt = blockIdx.x;
    int tid = threadIdx.x, w = tid >> 5, lane = tid & 31;
    int gr = lane >> 2, gq = lane & 3;
    int b = bh / H;
    int q0 = qt * 32;
    int mhalf = (w & 1) * 16;
    int kpart = w >> 1;
    int kb = kpart * 192;

    const uint2* KP = g_KP + ((size_t)(bh * D + d) * L) * 4;
    const uint2* QP = g_QP + ((size_t)(bh * D + d) * L) * 4;
    const float* mrow = mask + b * L;

    uint2 qa0 = QP[(size_t)(q0 + mhalf + gr) * 4 + gq];
    uint2 qa1 = QP[(size_t)(q0 + mhalf + gr + 8) * 4 + gq];
    unsigned ahi[2] = {qa0.x, qa1.x}, alo[2] = {qa0.y, qa1.y};

    float Zs[2] = {0, 0}, S2s[2] = {0, 0}, ESs[2] = {0, 0}, EMs[2] = {0, 0};

    #pragma unroll 4
    for (int nt = 0; nt < 24; nt++) {
        uint2 kv = KP[(size_t)(kb + nt * 8 + gr) * 4 + gq];

        float c[4] = {0.f, 0.f, 0.f, 0.f};
        mma_k8(c, ahi, kv.x);
        mma_k8(c, ahi, kv.y);
        mma_k8(c, alo, kv.x);

        float2 m2 = *(const float2*)(mrow + kb + nt * 8 + 2 * gq);
        float mk0 = m2.x * LOG2E, mk1 = m2.y * LOG2E;

        #pragma unroll
        for (int i = 0; i < 4; i++) {
            float s2l = fmaf(c[i], SCALE2, (i & 1) ? mk1 : mk0);
            float e = ex2f(s2l);
            int r = i >> 1;
            Zs[r] += e;
            S2s[r] = fmaf(e, e, S2s[r]);
            ESs[r] = fmaf(e, s2l, ESs[r]);
            EMs[r] = fmaxf(EMs[r], e);
        }
    }

    #pragma unroll
    for (int r = 0; r < 2; r++) {
        #pragma unroll
        for (int o = 1; o <= 2; o <<= 1) {
            Zs[r]  += __shfl_xor_sync(0xffffffffu, Zs[r],  o);
            S2s[r] += __shfl_xor_sync(0xffffffffu, S2s[r], o);
            ESs[r] += __shfl_xor_sync(0xffffffffu, ESs[r], o);
            EMs[r]  = fmaxf(EMs[r], __shfl_xor_sync(0xffffffffu, EMs[r], o));
        }
    }
    if (gq == 0) {
        #pragma unroll
        for (int r = 0; r < 2; r++) {
            int row = mhalf + gr + r * 8;
            sZ[kpart][row]  = Zs[r];
            sS2[kpart][row] = S2s[r];
            sES[kpart][row] = ESs[r];
            sEM[kpart][row] = EMs[r];
        }
    }
    __syncthreads();

    if (tid < 32) {
        int row = tid;
        float Z = 0, S2 = 0, ES = 0, EM = 0;
        #pragma unroll
        for (int j = 0; j < 4; j++) {
            Z += sZ[j][row]; S2 += sS2[j][row]; ES += sES[j][row];
            EM = fmaxf(EM, sEM[j][row]);
        }
        float invZ = 1.f / Z;
        g_invZ[((size_t)(bh * D + d)) * L + q0 + row] = invZ;
        float hh = S2 * invZ * invZ;
        float mm = EM * invZ;
        float ee = __logf(Z) - (ES * invZ) * LN2;
        #pragma unroll
        for (int o = 16; o; o >>= 1) {
            hh += __shfl_xor_sync(0xffffffffu, hh, o);
            mm += __shfl_xor_sync(0xffffffffu, mm, o);
            ee += __shfl_xor_sync(0xffffffffu, ee, o);
        }
        if (tid == 0) {
            size_t idx = ((size_t)(bh * D + d) * SQT + qt) * 3;
            g_part[idx + 0] = hh;
            g_part[idx + 1] = mm;
            g_part[idx + 2] = ee;
        }
    }
}

// ---------------------------------------------------------------------------
// Kernel 3: fused reduction + min-max norm + depth softmax (1 block).
// ---------------------------------------------------------------------------
__global__ __launch_bounds__(512)
void stats_weights()
{
    int t = threadIdx.x, w = t >> 5, lane = t & 31;
    __shared__ float st[2][4][D];

    int b = w >> 3, d = w & 7;
    double s2 = 0, mx = 0, en = 0;
    for (int i = lane; i < H * SQT; i += 32) {
        int h = i / SQT, qt = i - (i / SQT) * SQT;
        size_t idx = ((size_t)((b * H + h) * D + d) * SQT + qt) * 3;
        s2 += (double)g_part[idx + 0];
        mx += (double)g_part[idx + 1];
        en += (double)g_part[idx + 2];
    }
    #pragma unroll
    for (int o = 16; o; o >>= 1) {
        s2 += __shfl_xor_sync(0xffffffffu, s2, o);
        mx += __shfl_xor_sync(0xffffffffu, mx, o);
        en += __shfl_xor_sync(0xffffffffu, en, o);
    }
    if (lane == 0) {
        double n = (double)H * (double)L;
        double S2m = s2 / n;
        st[b][0][d] = (float)((S2m - 1.0 / (double)L) / (double)(L - 1));
        st[b][1][d] = (float)(mx / n);
        st[b][2][d] = (float)(en / n);
        st[b][3][d] = (float)S2m;
    }
    __syncthreads();
    if (t < 2) {
        int bb = t;
        float nrm[4][D];
        for (int j = 0; j < 4; j++) {
            float mn = st[bb][j][0], mxv = st[bb][j][0];
            for (int dd = 1; dd < D; dd++) {
                mn = fminf(mn, st[bb][j][dd]); mxv = fmaxf(mxv, st[bb][j][dd]);
            }
            float den = fmaxf(mxv - mn, 1e-12f);
            for (int dd = 0; dd < D; dd++) nrm[j][dd] = (st[bb][j][dd] - mn) / den;
        }
        float sc[D], mxs = -1e30f;
        for (int dd = 0; dd < D; dd++) {
            sc[dd] = 2.5f * (0.5f * nrm[0][dd] + 0.3f * nrm[1][dd]
                             + 0.2f * nrm[3][dd] - 0.4f * nrm[2][dd]);
            mxs = fmaxf(mxs, sc[dd]);
        }
        float Z = 0.f, e[D];
        for (int dd = 0; dd < D; dd++) { e[dd] = expf(sc[dd] - mxs); Z += e[dd]; }
        for (int dd = 0; dd < D; dd++) g_w[bb * D + dd] = e[dd] / Z;
    }
}

// ---------------------------------------------------------------------------
// Kernel 4: combine pass via HMMA m16n8k8, packed planes -> attn4.
// grid: (24, 3, BH), 256 threads.
// ---------------------------------------------------------------------------
__global__ __launch_bounds__(256)
void attn_combine(const float* __restrict__ mask, float* __restrict__ out_attn)
{
    __shared__ float sf[32][8];

    int qt = blockIdx.x, kr = blockIdx.y, bh = blockIdx.z;
    int tid = threadIdx.x, w = tid >> 5, lane = tid & 31;
    int gr = lane >> 2, gq = lane & 3;
    int b = bh / H;
    int q0 = qt * 32;
    int mhalf = (w & 1) * 16;
    int kb = kr * 256 + (w >> 1) * 64;
    const float* mrow = mask + b * L;

    {
        int r = tid >> 3, dd = tid & 7;
        sf[r][dd] = g_w[b * D + dd] *
                    g_invZ[((size_t)(bh * D + dd)) * L + q0 + r];
    }
    __syncthreads();

    float mkv[8][2];
    #pragma unroll
    for (int nt = 0; nt < 8; nt++) {
        float2 m2 = *(const float2*)(mrow + kb + nt * 8 + 2 * gq);
        mkv[nt][0] = m2.x * LOG2E;
        mkv[nt][1] = m2.y * LOG2E;
    }

    float acc[8][4];
    #pragma unroll
    for (int nt = 0; nt < 8; nt++)
        #pragma unroll
        for (int i = 0; i < 4; i++) acc[nt][i] = 0.f;

    for (int d = 0; d < D; d++) {
        const uint2* KP = g_KP + ((size_t)(bh * D + d) * L) * 4;
        const uint2* QP = g_QP + ((size_t)(bh * D + d) * L) * 4;

        uint2 qa0 = QP[(size_t)(q0 + mhalf + gr) * 4 + gq];
        uint2 qa1 = QP[(size_t)(q0 + mhalf + gr + 8) * 4 + gq];
        unsigned ahi[2] = {qa0.x, qa1.x}, alo[2] = {qa0.y, qa1.y};

        float fr0 = sf[mhalf + gr][d];
        float fr1 = sf[mhalf + gr + 8][d];

        #pragma unroll
        for (int nt = 0; nt < 8; nt++) {
            uint2 kv = KP[(size_t)(kb + nt * 8 + gr) * 4 + gq];

            float c[4] = {0.f, 0.f, 0.f, 0.f};
            mma_k8(c, ahi, kv.x);
            mma_k8(c, ahi, kv.y);
            mma_k8(c, alo, kv.x);

            #pragma unroll
            for (int i = 0; i < 4; i++) {
                float e = ex2f(fmaf(c[i], SCALE2, mkv[nt][i & 1]));
                acc[nt][i] = fmaf(e, (i >> 1) ? fr1 : fr0, acc[nt][i]);
            }
        }
    }

    int row0 = q0 + mhalf + gr;
    #pragma unroll
    for (int nt = 0; nt < 8; nt++) {
        int col = kb + nt * 8 + 2 * gq;
        *(float2*)(out_attn + ((size_t)bh * L + row0) * L + col) =
            make_float2(acc[nt][0], acc[nt][1]);
        *(float2*)(out_attn + ((size_t)bh * L + row0 + 8) * L + col) =
            make_float2(acc[nt][2], acc[nt][3]);
    }
}

// ---------------------------------------------------------------------------
// Kernel 5: ctx = attn4 @ V per bh via HMMA bf16x3 (qkv_mma structure).
// A = attn4 rows (128-tile), B = V[k][dh] (N=64), K = 768 in 24 chunks.
// grid: (6, BH), 256 threads.
// ---------------------------------------------------------------------------
__global__ __launch_bounds__(256)
void ctx_mma(const float* __restrict__ attn4, float* __restrict__ out)
{
    __shared__ unsigned Ahi[128*AP], Alo[128*AP];
    __shared__ unsigned Bhi[64*WP],  Blo[64*WP];

    int bh = blockIdx.y;
    int b = bh / H, h = bh % H;
    int tid = threadIdx.x, w = tid >> 5, lane = tid & 31;
    int rowBase = blockIdx.x * 128;
    int mrow = (w & 1) * 64;
    int ncol = (w >> 1) * 16;
    int gr = lane >> 2, gq = lane & 3;

    const float* A  = attn4 + (size_t)bh * L * L;
    const float* Vp = g_V + (size_t)bh * L * DH;

    float acc[4][2][4];
    #pragma unroll
    for (int mt = 0; mt < 4; mt++)
        #pragma unroll
        for (int nt = 0; nt < 2; nt++)
            #pragma unroll
            for (int i = 0; i < 4; i++) acc[mt][nt][i] = 0.f;

    for (int c = 0; c < 24; c++) {
        int kk = c * 32;
        __syncthreads();

        {
            int r = tid >> 1, cb = (tid & 1) * 16;
            const float* ap = A + (size_t)(rowBase + r) * L + kk + cb;
            #pragma unroll
            for (int j = 0; j < 4; j++) {
                float4 x = *(const float4*)(ap + j * 4);
                unsigned short h0, h1, h2, h3, l0, l1, l2, l3;
                split_bf(x.x, h0, l0); split_bf(x.y, h1, l1);
                split_bf(x.z, h2, l2); split_bf(x.w, h3, l3);
                int pi = r * AP + (tid & 1) * 8 + j * 2;
                Ahi[pi]     = pk(h0, h1);
                Ahi[pi + 1] = pk(h2, h3);
                Alo[pi]     = pk(l0, l1);
                Alo[pi + 1] = pk(l2, l3);
            }
        }
        {
            int n = tid & 63, k0 = (tid >> 6) * 8;
            unsigned short hi[8], lo[8];
            #pragma unroll
            for (int j = 0; j < 8; j++)
                split_bf(Vp[(size_t)(kk + k0 + j) * DH + n], hi[j], lo[j]);
            unsigned base = n * WP + (tid >> 6) * 4;
            *(uint4*)&Bhi[base] = make_uint4(pk(hi[0],hi[1]), pk(hi[2],hi[3]),
                                             pk(hi[4],hi[5]), pk(hi[6],hi[7]));
            *(uint4*)&Blo[base] = make_uint4(pk(lo[0],lo[1]), pk(lo[2],lo[3]),
                                             pk(lo[4],lo[5]), pk(lo[6],lo[7]));
        }
        __syncthreads();

        #pragma unroll
        for (int s = 0; s < 2; s++) {
            int pi = s * 8 + gq;
            unsigned afh[4][4], afl[4][4], bfh[2][2], bfl[2][2];
            #pragma unroll
            for (int mt = 0; mt < 4; mt++) {
                int rr = (mrow + mt * 16 + gr) * AP;
                afh[mt][0] = Ahi[rr + pi];
                afh[mt][1] = Ahi[rr + 8*AP + pi];
                afh[mt][2] = Ahi[rr + pi + 4];
                afh[mt][3] = Ahi[rr + 8*AP + pi + 4];
                afl[mt][0] = Alo[rr + pi];
                afl[mt][1] = Alo[rr + 8*AP + pi];
                afl[mt][2] = Alo[rr + pi + 4];
                afl[mt][3] = Alo[rr + 8*AP + pi + 4];
            }
            #pragma unroll
            for (int nt = 0; nt < 2; nt++) {
                int nn = (ncol + nt * 8 + gr) * WP;
                bfh[nt][0] = Bhi[nn + pi];
                bfh[nt][1] = Bhi[nn + pi + 4];
                bfl[nt][0] = Blo[nn + pi];
                bfl[nt][1] = Blo[nn + pi + 4];
            }
            #pragma unroll
            for (int mt = 0; mt < 4; mt++)
                #pragma unroll
                for (int nt = 0; nt < 2; nt++) {
                    mma_bf16(acc[mt][nt], afh[mt], bfh[nt]);
                    mma_bf16(acc[mt][nt], afh[mt], bfl[nt]);
                    mma_bf16(acc[mt][nt], afl[mt], bfh[nt]);
                }
        }
    }

    #pragma unroll
    for (int nt = 0; nt < 2; nt++) {
        int col = ncol + nt * 8 + gq * 2;   // 0..63 within head
        #pragma unroll
        for (int mt = 0; mt < 4; mt++) {
            int r0 = rowBase + mrow + mt * 16 + gr;
            #pragma unroll
            for (int half = 0; half < 2; half++) {
                int l = r0 + half * 8;
                float* dst = out + ((size_t)(b * L + l)) * E + h * DH + col;
                *(float2*)dst = make_float2(acc[mt][nt][half*2],
                                            acc[mt][nt][half*2 + 1]);
            }
        }
    }
}

// ---------------------------------------------------------------------------
extern "C" void kernel_launch(void* const* d_in, const int* in_sizes, int n_in,
                              void* d_out, int out_size)
{
    const float* X    = (const float*)d_in[0];
    const float* mask = (const float*)d_in[1];
    const float* Wq   = (const float*)d_in[2];
    const float* bq   = (const float*)d_in[3];
    const float* Wk   = (const float*)d_in[4];
    const float* bk   = (const float*)d_in[5];
    const float* Wv   = (const float*)d_in[6];
    const float* bv   = (const float*)d_in[7];

    float* out   = (float*)d_out;
    float* ctx   = out;                          // [B, L, E]
    float* attn4 = out + (size_t)B * L * E;      // [B, H, L, L]

    qkv_mma<<<dim3(12, 12, 3), 256>>>(X, Wq, bq, Wk, bk, Wv, bv);
    attn_stats<<<dim3(SQT, D, BH), 256>>>(mask);
    stats_weights<<<1, 512>>>();
    attn_combine<<<dim3(24, 3, BH), 256>>>(mask, attn4);
    ctx_mma<<<dim3(6, BH), 256>>>(attn4, ctx);
}

// round 15
// speedup vs baseline: 3.3235x; 1.0076x over previous
#include <cuda_runtime.h>
#include <cuda_bf16.h>
#include <math.h>

typedef unsigned long long ull;

#define B   2
#define L   768
#define H   12
#define DH  64
#define D   8
#define DS  8
#define E   768
#define BH  (B*H)

#define SQT 24            // stats q-tiles of 32 rows
#define NPART (BH*D*SQT)

#define SCALE2 0.51006972f     // (1/sqrt(8)) * log2(e)
#define LOG2E  1.4426950408889634f
#define LN2    0.6931471805599453f

// Q/K stored pre-split: uint2{hi,lo} packed bf16x2 per 2 dims.
__device__ uint2 g_QP[BH*D*L*4];
__device__ uint2 g_KP[BH*D*L*4];
__device__ float g_V[BH*L*DH];
__device__ float g_invZ[BH*D*L];
__device__ float g_part[NPART*3];
__device__ float g_w[B*D];

// pre-split input planes
__device__ unsigned gXhi[1536*384], gXlo[1536*384];          // [row][kpair]
__device__ unsigned gWhi[3*384*768], gWlo[3*384*768];        // [z][kpair][n]
__device__ float    g_mask2[B*L];                            // mask * log2(e)

// ---------------- math helpers ----------------
__device__ __forceinline__ float ex2f(float x) {
    float r; asm("ex2.approx.ftz.f32 %0, %1;" : "=f"(r) : "f"(x));
    return r;
}
__device__ __forceinline__ void split_bf(float x, unsigned short& hi, unsigned short& lo) {
    __nv_bfloat16 h = __float2bfloat16_rn(x);
    hi = __bfloat16_as_ushort(h);
    lo = __bfloat16_as_ushort(__float2bfloat16_rn(x - __bfloat162float(h)));
}
__device__ __forceinline__ unsigned pk(unsigned short a, unsigned short b) {
    return (unsigned)a | ((unsigned)b << 16);
}
__device__ __forceinline__ void mma_bf16(float* c, const unsigned* a, const unsigned* b) {
    asm volatile(
        "mma.sync.aligned.m16n8k16.row.col.f32.bf16.bf16.f32 "
        "{%0,%1,%2,%3}, {%4,%5,%6,%7}, {%8,%9}, {%0,%1,%2,%3};"
        : "+f"(c[0]), "+f"(c[1]), "+f"(c[2]), "+f"(c[3])
        : "r"(a[0]), "r"(a[1]), "r"(a[2]), "r"(a[3]), "r"(b[0]), "r"(b[1]));
}
__device__ __forceinline__ void mma_k8(float* c, const unsigned* a, unsigned b) {
    asm volatile(
        "mma.sync.aligned.m16n8k8.row.col.f32.bf16.bf16.f32 "
        "{%0,%1,%2,%3}, {%4,%5}, {%6}, {%0,%1,%2,%3};"
        : "+f"(c[0]), "+f"(c[1]), "+f"(c[2]), "+f"(c[3])
        : "r"(a[0]), "r"(a[1]), "r"(b));
}

// ---------------------------------------------------------------------------
// Kernel 0a: pre-split X into hi/lo planes + pre-scale mask.
// grid 2304 x 256: one thread per k-pair of X.
// ---------------------------------------------------------------------------
__global__ __launch_bounds__(256)
void presplit_x(const float* __restrict__ X, const float* __restrict__ mask)
{
    int gid = blockIdx.x * 256 + threadIdx.x;        // 0 .. 1536*384-1
    float2 v = *(const float2*)(X + (size_t)gid * 2);
    unsigned short h0, l0, h1, l1;
    split_bf(v.x, h0, l0); split_bf(v.y, h1, l1);
    gXhi[gid] = pk(h0, h1);
    gXlo[gid] = pk(l0, l1);
    if (gid < B * L) g_mask2[gid] = mask[gid] * LOG2E;
}

// ---------------------------------------------------------------------------
// Kernel 0b: pre-split W{q,k,v} into k-pair-major planes [z][kp][n].
// grid (3, 384, 3) x 256.
// ---------------------------------------------------------------------------
__global__ __launch_bounds__(256)
void presplit_w(const float* __restrict__ Wq, const float* __restrict__ Wk,
                const float* __restrict__ Wv)
{
    int n  = blockIdx.x * 256 + threadIdx.x;   // 0..767
    int kp = blockIdx.y;                        // 0..383
    int z  = blockIdx.z;
    const float* Wm = (z == 0) ? Wq : (z == 1) ? Wk : Wv;
    float a = Wm[(size_t)(2 * kp) * E + n];
    float b = Wm[(size_t)(2 * kp + 1) * E + n];
    unsigned short ha, la, hb, lb;
    split_bf(a, ha, la); split_bf(b, hb, lb);
    size_t o = ((size_t)(z * 384 + kp)) * E + n;
    gWhi[o] = pk(ha, hb);
    gWlo[o] = pk(la, lb);
}

// ---------------------------------------------------------------------------
// Kernel 1: QKV via HMMA bf16x3, loading pre-split planes (no in-kernel split
// of inputs).  Q/K epilogue stores packed planes; V stays fp32.
// grid (12, 12, 3), 256 threads.
// ---------------------------------------------------------------------------
#define AP 20   // A smem row stride (uints), %4==0 for uint4 STS
#define NP 72   // B smem row stride (uints): conflict-free frag reads

__global__ __launch_bounds__(256)
void qkv_mma(const float* __restrict__ bq, const float* __restrict__ bk,
             const float* __restrict__ bv)
{
    __shared__ unsigned Ahi[128*AP], Alo[128*AP];
    __shared__ unsigned Bh2[16*NP],  Bl2[16*NP];

    int z = blockIdx.z;
    const float* bm = (z == 0) ? bq : (z == 1) ? bk : bv;

    int tid = threadIdx.x, w = tid >> 5, lane = tid & 31;
    int rowBase = blockIdx.y * 128;
    int colBase = blockIdx.x * 64;
    int mrow = (w & 1) * 64;
    int ncol = (w >> 1) * 16;
    int gr = lane >> 2, gq = lane & 3;

    float acc[4][2][4];
    #pragma unroll
    for (int mt = 0; mt < 4; mt++)
        #pragma unroll
        for (int nt = 0; nt < 2; nt++)
            #pragma unroll
            for (int i = 0; i < 4; i++) acc[mt][nt][i] = 0.f;

    for (int c = 0; c < 24; c++) {
        __syncthreads();
        {   // A: X plane rows [rowBase..+128], kpairs [c*16 .. +16]
            int r = tid >> 1, kc = (tid & 1) * 8;
            size_t go = (size_t)(rowBase + r) * 384 + c * 16 + kc;
            *(uint4*)&Ahi[r*AP + kc]     = *(const uint4*)(gXhi + go);
            *(uint4*)&Ahi[r*AP + kc + 4] = *(const uint4*)(gXhi + go + 4);
            *(uint4*)&Alo[r*AP + kc]     = *(const uint4*)(gXlo + go);
            *(uint4*)&Alo[r*AP + kc + 4] = *(const uint4*)(gXlo + go + 4);
        }
        {   // B: W plane kpairs [c*16..+16], n [colBase..+64]
            int kp2 = tid >> 4, n4 = (tid & 15) * 4;
            size_t go = ((size_t)(z * 384 + c * 16 + kp2)) * E + colBase + n4;
            *(uint4*)&Bh2[kp2*NP + n4] = *(const uint4*)(gWhi + go);
            *(uint4*)&Bl2[kp2*NP + n4] = *(const uint4*)(gWlo + go);
        }
        __syncthreads();

        #pragma unroll
        for (int s = 0; s < 2; s++) {
            int pi = s * 8 + gq;
            unsigned afh[4][4], afl[4][4], bfh[2][2], bfl[2][2];
            #pragma unroll
            for (int mt = 0; mt < 4; mt++) {
                int rr = (mrow + mt * 16 + gr) * AP;
                afh[mt][0] = Ahi[rr + pi];
                afh[mt][1] = Ahi[rr + 8*AP + pi];
                afh[mt][2] = Ahi[rr + pi + 4];
                afh[mt][3] = Ahi[rr + 8*AP + pi + 4];
                afl[mt][0] = Alo[rr + pi];
                afl[mt][1] = Alo[rr + 8*AP + pi];
                afl[mt][2] = Alo[rr + pi + 4];
                afl[mt][3] = Alo[rr + 8*AP + pi + 4];
            }
            #pragma unroll
            for (int nt = 0; nt < 2; nt++) {
                int nn = ncol + nt * 8 + gr;
                bfh[nt][0] = Bh2[pi*NP + nn];
                bfh[nt][1] = Bh2[(pi + 4)*NP + nn];
                bfl[nt][0] = Bl2[pi*NP + nn];
                bfl[nt][1] = Bl2[(pi + 4)*NP + nn];
            }
            #pragma unroll
            for (int mt = 0; mt < 4; mt++)
                #pragma unroll
                for (int nt = 0; nt < 2; nt++) {
                    mma_bf16(acc[mt][nt], afh[mt], bfh[nt]);
                    mma_bf16(acc[mt][nt], afh[mt], bfl[nt]);
                    mma_bf16(acc[mt][nt], afl[mt], bfh[nt]);
                }
        }
    }

    #pragma unroll
    for (int nt = 0; nt < 2; nt++) {
        int col = colBase + ncol + nt * 8 + gq * 2;
        float b0 = bm[col], b1 = bm[col + 1];
        int h = col >> 6;
        int dd = (col >> 3) & 7;
        int pair = (col >> 1) & 3;
        #pragma unroll
        for (int mt = 0; mt < 4; mt++) {
            int r0 = rowBase + mrow + mt * 16 + gr;
            #pragma unroll
            for (int half = 0; half < 2; half++) {
                int m = r0 + half * 8;
                int bb = m / L, l = m - bb * L;
                float v0 = acc[mt][nt][half*2]     + b0;
                float v1 = acc[mt][nt][half*2 + 1] + b1;
                if (z < 2) {
                    unsigned short h0, l0, h1, l1;
                    split_bf(v0, h0, l0); split_bf(v1, h1, l1);
                    uint2* dst = (z == 0 ? g_QP : g_KP)
                        + (((size_t)(bb * H + h) * D + dd) * L + l) * 4 + pair;
                    *dst = make_uint2(pk(h0, h1), pk(l0, l1));
                } else {
                    float* dst = g_V + ((size_t)(bb * H + h) * L + l) * 64 + (col & 63);
                    *(float2*)dst = make_float2(v0, v1);
                }
            }
        }
    }
}

// ---------------------------------------------------------------------------
// Kernel 2: stats pass via HMMA m16n8k8, rolling pointers, pre-scaled mask.
// grid: (SQT, D, BH), 256 threads.
// ---------------------------------------------------------------------------
__global__ __launch_bounds__(256)
void attn_stats()
{
    __shared__ float sZ[4][32], sS2[4][32], sES[4][32], sEM[4][32];

    int bh = blockIdx.z, d = blockIdx.y, qt = blockIdx.x;
    int tid = threadIdx.x, w = tid >> 5, lane = tid & 31;
    int gr = lane >> 2, gq = lane & 3;
    int b = bh / H;
    int q0 = qt * 32;
    int mhalf = (w & 1) * 16;
    int kpart = w >> 1;
    int kb = kpart * 192;

    const uint2* QPb = g_QP + ((size_t)(bh * D + d) * L) * 4;
    uint2 qa0 = QPb[(q0 + mhalf + gr) * 4 + gq];
    uint2 qa1 = QPb[(q0 + mhalf + gr + 8) * 4 + gq];
    unsigned ahi[2] = {qa0.x, qa1.x}, alo[2] = {qa0.y, qa1.y};

    const uint2* kp_ = g_KP + ((size_t)(bh * D + d) * L + kb + gr) * 4 + gq;
    const float* m2p = g_mask2 + b * L + kb + 2 * gq;

    float Zs[2] = {0, 0}, S2s[2] = {0, 0}, ESs[2] = {0, 0}, EMs[2] = {0, 0};

    for (int o = 0; o < 6; o++) {
        #pragma unroll
        for (int ni = 0; ni < 4; ni++) {
            uint2 kv = kp_[ni * 32];
            float2 m2 = *(const float2*)(m2p + ni * 8);

            float c[4] = {0.f, 0.f, 0.f, 0.f};
            mma_k8(c, ahi, kv.x);
            mma_k8(c, ahi, kv.y);
            mma_k8(c, alo, kv.x);

            #pragma unroll
            for (int i = 0; i < 4; i++) {
                float s2l = fmaf(c[i], SCALE2, (i & 1) ? m2.y : m2.x);
                float e = ex2f(s2l);
                int r = i >> 1;
                Zs[r] += e;
                S2s[r] = fmaf(e, e, S2s[r]);
                ESs[r] = fmaf(e, s2l, ESs[r]);
                EMs[r] = fmaxf(EMs[r], e);
            }
        }
        kp_ += 128;
        m2p += 32;
    }

    #pragma unroll
    for (int r = 0; r < 2; r++) {
        #pragma unroll
        for (int o = 1; o <= 2; o <<= 1) {
            Zs[r]  += __shfl_xor_sync(0xffffffffu, Zs[r],  o);
            S2s[r] += __shfl_xor_sync(0xffffffffu, S2s[r], o);
            ESs[r] += __shfl_xor_sync(0xffffffffu, ESs[r], o);
            EMs[r]  = fmaxf(EMs[r], __shfl_xor_sync(0xffffffffu, EMs[r], o));
        }
    }
    if (gq == 0) {
        #pragma unroll
        for (int r = 0; r < 2; r++) {
            int row = mhalf + gr + r * 8;
            sZ[kpart][row]  = Zs[r];
            sS2[kpart][row] = S2s[r];
            sES[kpart][row] = ESs[r];
            sEM[kpart][row] = EMs[r];
        }
    }
    __syncthreads();

    if (tid < 32) {
        int row = tid;
        float Z = 0, S2 = 0, ES = 0, EM = 0;
        #pragma unroll
        for (int j = 0; j < 4; j++) {
            Z += sZ[j][row]; S2 += sS2[j][row]; ES += sES[j][row];
            EM = fmaxf(EM, sEM[j][row]);
        }
        float invZ = 1.f / Z;
        g_invZ[((size_t)(bh * D + d)) * L + q0 + row] = invZ;
        float hh = S2 * invZ * invZ;
        float mm = EM * invZ;
        float ee = __logf(Z) - (ES * invZ) * LN2;
        #pragma unroll
        for (int o = 16; o; o >>= 1) {
            hh += __shfl_xor_sync(0xffffffffu, hh, o);
            mm += __shfl_xor_sync(0xffffffffu, mm, o);
            ee += __shfl_xor_sync(0xffffffffu, ee, o);
        }
        if (tid == 0) {
            size_t idx = ((size_t)(bh * D + d) * SQT + qt) * 3;
            g_part[idx + 0] = hh;
            g_part[idx + 1] = mm;
            g_part[idx + 2] = ee;
        }
    }
}

// ---------------------------------------------------------------------------
// Kernel 3: fused reduction + min-max norm + depth softmax (1 block).
// ---------------------------------------------------------------------------
__global__ __launch_bounds__(512)
void stats_weights()
{
    int t = threadIdx.x, w = t >> 5, lane = t & 31;
    __shared__ float st[2][4][D];

    int b = w >> 3, d = w & 7;
    double s2 = 0, mx = 0, en = 0;
    for (int i = lane; i < H * SQT; i += 32) {
        int h = i / SQT, qt = i - (i / SQT) * SQT;
        size_t idx = ((size_t)((b * H + h) * D + d) * SQT + qt) * 3;
        s2 += (double)g_part[idx + 0];
        mx += (double)g_part[idx + 1];
        en += (double)g_part[idx + 2];
    }
    #pragma unroll
    for (int o = 16; o; o >>= 1) {
        s2 += __shfl_xor_sync(0xffffffffu, s2, o);
        mx += __shfl_xor_sync(0xffffffffu, mx, o);
        en += __shfl_xor_sync(0xffffffffu, en, o);
    }
    if (lane == 0) {
        double n = (double)H * (double)L;
        double S2m = s2 / n;
        st[b][0][d] = (float)((S2m - 1.0 / (double)L) / (double)(L - 1));
        st[b][1][d] = (float)(mx / n);
        st[b][2][d] = (float)(en / n);
        st[b][3][d] = (float)S2m;
    }
    __syncthreads();
    if (t < 2) {
        int bb = t;
        float nrm[4][D];
        for (int j = 0; j < 4; j++) {
            float mn = st[bb][j][0], mxv = st[bb][j][0];
            for (int dd = 1; dd < D; dd++) {
                mn = fminf(mn, st[bb][j][dd]); mxv = fmaxf(mxv, st[bb][j][dd]);
            }
            float den = fmaxf(mxv - mn, 1e-12f);
            for (int dd = 0; dd < D; dd++) nrm[j][dd] = (st[bb][j][dd] - mn) / den;
        }
        float sc[D], mxs = -1e30f;
        for (int dd = 0; dd < D; dd++) {
            sc[dd] = 2.5f * (0.5f * nrm[0][dd] + 0.3f * nrm[1][dd]
                             + 0.2f * nrm[3][dd] - 0.4f * nrm[2][dd]);
            mxs = fmaxf(mxs, sc[dd]);
        }
        float Z = 0.f, e[D];
        for (int dd = 0; dd < D; dd++) { e[dd] = expf(sc[dd] - mxs); Z += e[dd]; }
        for (int dd = 0; dd < D; dd++) g_w[bb * D + dd] = e[dd] / Z;
    }
}

// ---------------------------------------------------------------------------
// Kernel 4: combine pass via HMMA m16n8k8, rolling pointers -> attn4.
// grid: (24, 3, BH), 256 threads.
// ---------------------------------------------------------------------------
__global__ __launch_bounds__(256)
void attn_combine(float* __restrict__ out_attn)
{
    __shared__ float sf[32][8];

    int qt = blockIdx.x, kr = blockIdx.y, bh = blockIdx.z;
    int tid = threadIdx.x, w = tid >> 5, lane = tid & 31;
    int gr = lane >> 2, gq = lane & 3;
    int b = bh / H;
    int q0 = qt * 32;
    int mhalf = (w & 1) * 16;
    int kb = kr * 256 + (w >> 1) * 64;

    {
        int r = tid >> 3, dd = tid & 7;
        sf[r][dd] = g_w[b * D + dd] *
                    g_invZ[((size_t)(bh * D + dd)) * L + q0 + r];
    }
    __syncthreads();

    float mkv[8][2];
    #pragma unroll
    for (int nt = 0; nt < 8; nt++) {
        float2 m2 = *(const float2*)(g_mask2 + b * L + kb + nt * 8 + 2 * gq);
        mkv[nt][0] = m2.x;
        mkv[nt][1] = m2.y;
    }

    float acc[8][4];
    #pragma unroll
    for (int nt = 0; nt < 8; nt++)
        #pragma unroll
        for (int i = 0; i < 4; i++) acc[nt][i] = 0.f;

    const uint2* qpd = g_QP + ((size_t)(bh * D) * L + q0 + mhalf + gr) * 4 + gq;
    const uint2* kpd = g_KP + ((size_t)(bh * D) * L + kb + gr) * 4 + gq;
    const float* sfp = &sf[mhalf + gr][0];

    #pragma unroll 2
    for (int d = 0; d < D; d++) {
        uint2 qa0 = qpd[0];
        uint2 qa1 = qpd[32];           // +8 rows * 4 pairs
        unsigned ahi[2] = {qa0.x, qa1.x}, alo[2] = {qa0.y, qa1.y};

        float fr0 = sfp[d];
        float fr1 = sfp[8 * 8 + d];    // +8 rows * 8 depths

        #pragma unroll
        for (int nt = 0; nt < 8; nt++) {
            uint2 kv = kpd[nt * 32];

            float c[4] = {0.f, 0.f, 0.f, 0.f};
            mma_k8(c, ahi, kv.x);
            mma_k8(c, ahi, kv.y);
            mma_k8(c, alo, kv.x);

            #pragma unroll
            for (int i = 0; i < 4; i++) {
                float e = ex2f(fmaf(c[i], SCALE2, mkv[nt][i & 1]));
                acc[nt][i] = fmaf(e, (i >> 1) ? fr1 : fr0, acc[nt][i]);
            }
        }
        qpd += L * 4;
        kpd += L * 4;
    }

    int row0 = q0 + mhalf + gr;
    #pragma unroll
    for (int nt = 0; nt < 8; nt++) {
        int col = kb + nt * 8 + 2 * gq;
        *(float2*)(out_attn + ((size_t)bh * L + row0) * L + col) =
            make_float2(acc[nt][0], acc[nt][1]);
        *(float2*)(out_attn + ((size_t)bh * L + row0 + 8) * L + col) =
            make_float2(acc[nt][2], acc[nt][3]);
    }
}

// ---------------------------------------------------------------------------
// Kernel 5: ctx = attn4 @ V per bh via HMMA bf16x3 (unchanged from R14).
// grid: (6, BH), 256 threads.
// ---------------------------------------------------------------------------
#define CAP 18
#define CWP 20

__global__ __launch_bounds__(256)
void ctx_mma(const float* __restrict__ attn4, float* __restrict__ out)
{
    __shared__ unsigned Ahi[128*CAP], Alo[128*CAP];
    __shared__ unsigned Bhi[64*CWP],  Blo[64*CWP];

    int bh = blockIdx.y;
    int b = bh / H, h = bh % H;
    int tid = threadIdx.x, w = tid >> 5, lane = tid & 31;
    int rowBase = blockIdx.x * 128;
    int mrow = (w & 1) * 64;
    int ncol = (w >> 1) * 16;
    int gr = lane >> 2, gq = lane & 3;

    const float* A  = attn4 + (size_t)bh * L * L;
    const float* Vp = g_V + (size_t)bh * L * DH;

    float acc[4][2][4];
    #pragma unroll
    for (int mt = 0; mt < 4; mt++)
        #pragma unroll
        for (int nt = 0; nt < 2; nt++)
            #pragma unroll
            for (int i = 0; i < 4; i++) acc[mt][nt][i] = 0.f;

    for (int c = 0; c < 24; c++) {
        int kk = c * 32;
        __syncthreads();

        {
            int r = tid >> 1, cb = (tid & 1) * 16;
            const float* ap = A + (size_t)(rowBase + r) * L + kk + cb;
            #pragma unroll
            for (int j = 0; j < 4; j++) {
                float4 x = *(const float4*)(ap + j * 4);
                unsigned short h0, h1, h2, h3, l0, l1, l2, l3;
                split_bf(x.x, h0, l0); split_bf(x.y, h1, l1);
                split_bf(x.z, h2, l2); split_bf(x.w, h3, l3);
                int pi = r * CAP + (tid & 1) * 8 + j * 2;
                Ahi[pi]     = pk(h0, h1);
                Ahi[pi + 1] = pk(h2, h3);
                Alo[pi]     = pk(l0, l1);
                Alo[pi + 1] = pk(l2, l3);
            }
        }
        {
            int n = tid & 63, k0 = (tid >> 6) * 8;
            unsigned short hi[8], lo[8];
            #pragma unroll
            for (int j = 0; j < 8; j++)
                split_bf(Vp[(size_t)(kk + k0 + j) * DH + n], hi[j], lo[j]);
            unsigned base = n * CWP + (tid >> 6) * 4;
            *(uint4*)&Bhi[base] = make_uint4(pk(hi[0],hi[1]), pk(hi[2],hi[3]),
                                             pk(hi[4],hi[5]), pk(hi[6],hi[7]));
            *(uint4*)&Blo[base] = make_uint4(pk(lo[0],lo[1]), pk(lo[2],lo[3]),
                                             pk(lo[4],lo[5]), pk(lo[6],lo[7]));
        }
        __syncthreads();

        #pragma unroll
        for (int s = 0; s < 2; s++) {
            int pi = s * 8 + gq;
            unsigned afh[4][4], afl[4][4], bfh[2][2], bfl[2][2];
            #pragma unroll
            for (int mt = 0; mt < 4; mt++) {
                int rr = (mrow + mt * 16 + gr) * CAP;
                afh[mt][0] = Ahi[rr + pi];
                afh[mt][1] = Ahi[rr + 8*CAP + pi];
                afh[mt][2] = Ahi[rr + pi + 4];
                afh[mt][3] = Ahi[rr + 8*CAP + pi + 4];
                afl[mt][0] = Alo[rr + pi];
                afl[mt][1] = Alo[rr + 8*CAP + pi];
                afl[mt][2] = Alo[rr + pi + 4];
                afl[mt][3] = Alo[rr + 8*CAP + pi + 4];
            }
            #pragma unroll
            for (int nt = 0; nt < 2; nt++) {
                int nn = (ncol + nt * 8 + gr) * CWP;
                bfh[nt][0] = Bhi[nn + pi];
                bfh[nt][1] = Bhi[nn + pi + 4];
                bfl[nt][0] = Blo[nn + pi];
                bfl[nt][1] = Blo[nn + pi + 4];
            }
            #pragma unroll
            for (int mt = 0; mt < 4; mt++)
                #pragma unroll
                for (int nt = 0; nt < 2; nt++) {
                    mma_bf16(acc[mt][nt], afh[mt], bfh[nt]);
                    mma_bf16(acc[mt][nt], afh[mt], bfl[nt]);
                    mma_bf16(acc[mt][nt], afl[mt], bfh[nt]);
                }
        }
    }

    #pragma unroll
    for (int nt = 0; nt < 2; nt++) {
        int col = ncol + nt * 8 + gq * 2;
        #pragma unroll
        for (int mt = 0; mt < 4; mt++) {
            int r0 = rowBase + mrow + mt * 16 + gr;
            #pragma unroll
            for (int half = 0; half < 2; half++) {
                int l = r0 + half * 8;
                float* dst = out + ((size_t)(b * L + l)) * E + h * DH + col;
                *(float2*)dst = make_float2(acc[mt][nt][half*2],
                                            acc[mt][nt][half*2 + 1]);
            }
        }
    }
}

// ---------------------------------------------------------------------------
extern "C" void kernel_launch(void* const* d_in, const int* in_sizes, int n_in,
                              void* d_out, int out_size)
{
    const float* X    = (const float*)d_in[0];
    const float* mask = (const float*)d_in[1];
    const float* Wq   = (const float*)d_in[2];
    const float* bq   = (const float*)d_in[3];
    const float* Wk   = (const float*)d_in[4];
    const float* bk   = (const float*)d_in[5];
    const float* Wv   = (const float*)d_in[6];
    const float* bv   = (const float*)d_in[7];

    float* out   = (float*)d_out;
    float* ctx   = out;                          // [B, L, E]
    float* attn4 = out + (size_t)B * L * E;      // [B, H, L, L]

    presplit_x<<<2304, 256>>>(X, mask);
    presplit_w<<<dim3(3, 384, 3), 256>>>(Wq, Wk, Wv);
    qkv_mma<<<dim3(12, 12, 3), 256>>>(bq, bk, bv);
    attn_stats<<<dim3(SQT, D, BH), 256>>>();
    stats_weights<<<1, 512>>>();
    attn_combine<<<dim3(24, 3, BH), 256>>>(attn4);
    ctx_mma<<<dim3(6, BH), 256>>>(attn4, ctx);
}